// round 12
// baseline (speedup 1.0000x reference)
#include <cuda_runtime.h>
#include <cuda_fp16.h>
#include <cstdint>

#define NMAX 200000
#define PCAP 65536
#define LDSROW 72              // 64 K-halves + 8 pad (144B rows)
#define STAGE_SP 36864         // sparse kernel: A 128x72x2 + B 128x72x2
#define SMEM_SP (3 * STAGE_SP + 512)
#define STAGE_SF 55296         // self kernel: A 128x72x2 + B 256x72x2
#define SMEM_SF (3 * STAGE_SF + 512)

// ---------------- device scratch ----------------
__device__ __half g_h1[(size_t)NMAX * 256];
__device__ float  g_acc[(size_t)NMAX * 256];
__device__ __half g_w2t[9 * 256 * 256];        // W2^T fp16 [k][cout][cin]
__device__ int  g_src[9][PCAP];
__device__ int  g_dst[9][PCAP];
__device__ int  g_cnt[9];
__device__ float g_counts[8];
__device__ unsigned char g_flag[NMAX];

// ---------------- prep (+ batch counting, fused) ----------------
__global__ void prep_kernel(float* out, const int* __restrict__ bids, int n) {
    __shared__ int loc[8];
    if (threadIdx.x < 8) loc[threadIdx.x] = 0;
    __syncthreads();
    int t = blockIdx.x * blockDim.x + threadIdx.x;
    int stride = gridDim.x * blockDim.x;
    for (int i = t; i < 2048; i += stride) out[i] = 0.f;
    for (int i = t; i < NMAX / 4; i += stride) ((int*)g_flag)[i] = 0;
    if (t < 9) g_cnt[t] = 0;
    if (t < 8) g_counts[t] = 0.f;
    for (int i = t; i < n; i += stride) atomicAdd(&loc[bids[i]], 1);
    __syncthreads();
    if (threadIdx.x < 8 && loc[threadIdx.x])
        atomicAdd(&g_counts[threadIdx.x], (float)loc[threadIdx.x]);
}

// ---------------- W2 transpose -> fp16 (coalesced smem transpose) ---------
__global__ void convw2_kernel(const float* __restrict__ W2) {
    __shared__ float tile[32][33];
    int k = blockIdx.z;
    int ci0 = blockIdx.x * 32, co0 = blockIdx.y * 32;
    int tx = threadIdx.x, ty = threadIdx.y;
    #pragma unroll
    for (int r = 0; r < 32; r += 8) {
        int ci = ci0 + ty + r;
        tile[ty + r][tx] = W2[(k << 16) + (ci << 8) + co0 + tx];
    }
    __syncthreads();
    #pragma unroll
    for (int r = 0; r < 32; r += 8) {
        int co = co0 + ty + r;
        g_w2t[(k << 16) + (co << 8) + ci0 + tx] = __float2half_rn(tile[tx][ty + r]);
    }
}

// ---------------- layer 1: warp per point ----------------
__global__ void layer1_kernel(const float* __restrict__ feats,
                              const float* __restrict__ W1,
                              const int* __restrict__ nbr, int n) {
    int gw = (blockIdx.x * blockDim.x + threadIdx.x) >> 5;
    int lane = threadIdx.x & 31;
    int nw = (gridDim.x * blockDim.x) >> 5;
    for (int i = gw; i < n; i += nw) {
        int j = -1; float f0 = 0.f, f1 = 0.f, f2 = 0.f;
        if (lane < 9) {
            j = nbr[(size_t)i * 9 + lane];
            if (j >= 0) {
                f0 = feats[(size_t)j * 3 + 0];
                f1 = feats[(size_t)j * 3 + 1];
                f2 = feats[(size_t)j * 3 + 2];
            }
        }
        unsigned vm = __ballot_sync(0xffffffffu, lane < 9 && j >= 0);
        if (lane < 9 && j >= 0 && lane != 4) {
            int pos = atomicAdd(&g_cnt[lane], 1);
            if (pos < PCAP) { g_src[lane][pos] = j; g_dst[lane][pos] = i; }
        }
        if (lane == 0) g_flag[i] = (vm & 0x1EFu) ? 1 : 0;
        float acc[8];
        #pragma unroll
        for (int q = 0; q < 8; q++) acc[q] = 0.f;
        int c0 = lane * 8;
        #pragma unroll
        for (int k = 0; k < 9; k++) {
            if (vm & (1u << k)) {
                float a0 = __shfl_sync(0xffffffffu, f0, k);
                float a1 = __shfl_sync(0xffffffffu, f1, k);
                float a2 = __shfl_sync(0xffffffffu, f2, k);
                const float4* w0 = (const float4*)(W1 + (k * 3 + 0) * 256 + c0);
                const float4* w1 = (const float4*)(W1 + (k * 3 + 1) * 256 + c0);
                const float4* w2 = (const float4*)(W1 + (k * 3 + 2) * 256 + c0);
                float4 x0 = w0[0], x1 = w0[1];
                float4 y0 = w1[0], y1 = w1[1];
                float4 z0 = w2[0], z1 = w2[1];
                acc[0] += a0 * x0.x + a1 * y0.x + a2 * z0.x;
                acc[1] += a0 * x0.y + a1 * y0.y + a2 * z0.y;
                acc[2] += a0 * x0.z + a1 * y0.z + a2 * z0.z;
                acc[3] += a0 * x0.w + a1 * y0.w + a2 * z0.w;
                acc[4] += a0 * x1.x + a1 * y1.x + a2 * z1.x;
                acc[5] += a0 * x1.y + a1 * y1.y + a2 * z1.y;
                acc[6] += a0 * x1.z + a1 * y1.z + a2 * z1.z;
                acc[7] += a0 * x1.w + a1 * y1.w + a2 * z1.w;
            }
        }
        __half2 o[4];
        #pragma unroll
        for (int q = 0; q < 4; q++) {
            float u = acc[2 * q],     v = acc[2 * q + 1];
            o[q] = __floats2half2_rn(u > 0.f ? u : 0.f, v > 0.f ? v : 0.f);
        }
        *(uint4*)(g_h1 + (size_t)i * 256 + c0) = *(uint4*)o;
    }
}

// ---------------- zero g_acc rows right before the sparse scatter ---------
// (placement load-bearing: keeps zeroed lines L2-hot for the atomics)
__global__ void zero_rows_kernel() {
    int tap = blockIdx.y;
    int kk = (tap < 4) ? tap : tap + 1;
    int cnt = g_cnt[kk]; if (cnt > PCAP) cnt = PCAP;
    float4 z = make_float4(0.f, 0.f, 0.f, 0.f);
    for (int p = blockIdx.x; p < cnt; p += gridDim.x) {
        int row = g_dst[kk][p];
        float4* dst = (float4*)(g_acc + (size_t)row * 256);
        for (int e = threadIdx.x; e < 64; e += blockDim.x) dst[e] = z;
    }
}

// ---------------- GEMM helpers ----------------
__device__ __forceinline__ void mma16816(float c[4], const uint32_t a[4],
                                         const uint32_t* b) {
    asm volatile(
        "mma.sync.aligned.m16n8k16.row.col.f32.f16.f16.f32 "
        "{%0,%1,%2,%3}, {%4,%5,%6,%7}, {%8,%9}, {%0,%1,%2,%3};\n"
        : "+f"(c[0]), "+f"(c[1]), "+f"(c[2]), "+f"(c[3])
        : "r"(a[0]), "r"(a[1]), "r"(a[2]), "r"(a[3]), "r"(b[0]), "r"(b[1]));
}
__device__ __forceinline__ void ldmx4(uint32_t* r, uint32_t saddr) {
    asm volatile("ldmatrix.sync.aligned.m8n8.x4.shared.b16 {%0,%1,%2,%3}, [%4];"
                 : "=r"(r[0]), "=r"(r[1]), "=r"(r[2]), "=r"(r[3]) : "r"(saddr));
}
__device__ __forceinline__ void red_v2(float* p, float v0, float v1) {
    asm volatile("red.global.add.v2.f32 [%0], {%1,%2};"
                 :: "l"(p), "f"(v0), "f"(v1) : "memory");
}
__device__ __forceinline__ void cp16(uint32_t saddr, const void* g, bool valid) {
    int sz = valid ? 16 : 0;
    asm volatile("cp.async.cg.shared.global [%0], [%1], 16, %2;"
                 :: "r"(saddr), "l"(g), "r"(sz));
}

// ---------------- sparse GEMM (R11, unchanged): 128Mx128N, KC=64 ----------
__global__ __launch_bounds__(256, 2) void gemm_kernel() {
    extern __shared__ __align__(16) char dsm[];
    uint32_t sbase = (uint32_t)__cvta_generic_to_shared(dsm);
    int tid = threadIdx.x, lane = tid & 31, warp = tid >> 5;
    int wm = warp >> 2, wn = warp & 3;
    int g = lane >> 2, t = lane & 3;

    int y = blockIdx.y;
    int tap = y >> 1, nhalf = y & 1;
    int kk = (tap < 4) ? tap : tap + 1;
    int cnt = g_cnt[kk]; if (cnt > PCAP) cnt = PCAP;
    int tiles = (cnt + 127) >> 7;
    const int* srcl = g_src[kk];
    const int* dstl = g_dst[kk];
    const __half* BW = g_w2t + (size_t)kk * 65536 + (size_t)nhalf * 128 * 256;

    int r_ld = tid >> 3, q_ld = tid & 7;

    for (int tile = blockIdx.x; tile < tiles; tile += gridDim.x) {
        float acc[4][4][4];
        #pragma unroll
        for (int a = 0; a < 4; a++)
            #pragma unroll
            for (int b = 0; b < 4; b++)
                #pragma unroll
                for (int d = 0; d < 4; d++) acc[a][b][d] = 0.f;

        const __half* asrc[4]; bool aval[4];
        #pragma unroll
        for (int i = 0; i < 4; i++) {
            int ar = tile * 128 + r_ld + i * 32;
            aval[i] = (ar < cnt);
            asrc[i] = g_h1 + (size_t)(aval[i] ? srcl[ar] : 0) * 256;
        }

        auto issue = [&](int c) {
            if (c < 4) {
                int kc = c * 64;
                uint32_t sa = sbase + (uint32_t)(c % 3) * STAGE_SP;
                #pragma unroll
                for (int i = 0; i < 4; i++) {
                    int row = r_ld + i * 32;
                    uint32_t da = sa + (row * LDSROW + q_ld * 8) * 2;
                    cp16(da, asrc[i] + kc + q_ld * 8, aval[i]);
                    cp16(da + 18432, BW + row * 256 + kc + q_ld * 8, true);
                }
            }
            asm volatile("cp.async.commit_group;");
        };

        issue(0); issue(1);
        #pragma unroll 1
        for (int c = 0; c < 4; c++) {
            asm volatile("cp.async.wait_group 1;");
            __syncthreads();
            issue(c + 2);
            uint32_t As_u = sbase + (uint32_t)(c % 3) * STAGE_SP;
            uint32_t Bs_u = As_u + 18432;
            #pragma unroll
            for (int ks = 0; ks < 64; ks += 16) {
                uint32_t afr[4][4];
                #pragma unroll
                for (int mi = 0; mi < 4; mi++) {
                    int row = wm * 64 + mi * 16 + ((lane >> 3) & 1) * 8 + (lane & 7);
                    int kofs = ks + ((lane >> 4) << 3);
                    ldmx4(afr[mi], As_u + (row * LDSROW + kofs) * 2);
                }
                #pragma unroll
                for (int p = 0; p < 2; p++) {
                    uint32_t bb[4];
                    int row = wn * 32 + p * 16 + ((lane >> 4) << 3) + (lane & 7);
                    int kofs = ks + (((lane >> 3) & 1) << 3);
                    ldmx4(bb, Bs_u + (row * LDSROW + kofs) * 2);
                    #pragma unroll
                    for (int mi = 0; mi < 4; mi++) {
                        mma16816(acc[mi][2 * p],     afr[mi], bb);
                        mma16816(acc[mi][2 * p + 1], afr[mi], bb + 2);
                    }
                }
            }
        }
        __syncthreads();

        #pragma unroll
        for (int mi = 0; mi < 4; mi++) {
            int rr = wm * 64 + mi * 16 + g;
            #pragma unroll
            for (int ni = 0; ni < 4; ni++) {
                int col = nhalf * 128 + wn * 32 + ni * 8 + 2 * t;
                int ra = tile * 128 + rr, rb = ra + 8;
                if (ra < cnt)
                    red_v2(g_acc + (size_t)dstl[ra] * 256 + col,
                           acc[mi][ni][0], acc[mi][ni][1]);
                if (rb < cnt)
                    red_v2(g_acc + (size_t)dstl[rb] * 256 + col,
                           acc[mi][ni][2], acc[mi][ni][3]);
            }
        }
    }
}

// ---------------- self GEMM: 128M x 256N single pass, 512 threads ---------
__global__ __launch_bounds__(512, 1) void self_gemm_kernel(int n,
                                                           const int* __restrict__ bids,
                                                           float* __restrict__ out) {
    extern __shared__ __align__(16) char dsm[];
    uint32_t sbase = (uint32_t)__cvta_generic_to_shared(dsm);
    int tid = threadIdx.x, lane = tid & 31, warp = tid >> 5;
    int wm = warp >> 3, wn = warp & 7;    // 2 x 8 warps -> warp tile 64M x 32N
    int g = lane >> 2, t = lane & 3;

    int tiles = (n + 127) >> 7;
    const __half* BW = g_w2t + 4 * 65536;   // tap 4, full 256 cols

    int r_ld = tid >> 3, q_ld = tid & 7;    // r_ld 0..63, 8 x 16B slots

    for (int tile = blockIdx.x; tile < tiles; tile += gridDim.x) {
        float acc[4][4][4];
        #pragma unroll
        for (int a = 0; a < 4; a++)
            #pragma unroll
            for (int b = 0; b < 4; b++)
                #pragma unroll
                for (int d = 0; d < 4; d++) acc[a][b][d] = 0.f;

        const __half* asrc[2]; bool aval[2];
        #pragma unroll
        for (int i = 0; i < 2; i++) {
            int ar = tile * 128 + r_ld + i * 64;
            aval[i] = (ar < n);
            asrc[i] = g_h1 + (size_t)(aval[i] ? ar : 0) * 256;
        }

        auto issue = [&](int c) {
            if (c < 4) {
                int kc = c * 64;
                uint32_t sa = sbase + (uint32_t)(c % 3) * STAGE_SF;
                #pragma unroll
                for (int i = 0; i < 2; i++) {      // A: 128 rows
                    int row = r_ld + i * 64;
                    cp16(sa + (row * LDSROW + q_ld * 8) * 2,
                         asrc[i] + kc + q_ld * 8, aval[i]);
                }
                #pragma unroll
                for (int i = 0; i < 4; i++) {      // B: 256 rows
                    int row = r_ld + i * 64;
                    cp16(sa + 18432 + (row * LDSROW + q_ld * 8) * 2,
                         BW + row * 256 + kc + q_ld * 8, true);
                }
            }
            asm volatile("cp.async.commit_group;");
        };

        issue(0); issue(1);
        #pragma unroll 1
        for (int c = 0; c < 4; c++) {
            asm volatile("cp.async.wait_group 1;");
            __syncthreads();
            issue(c + 2);
            uint32_t As_u = sbase + (uint32_t)(c % 3) * STAGE_SF;
            uint32_t Bs_u = As_u + 18432;
            #pragma unroll
            for (int ks = 0; ks < 64; ks += 16) {
                uint32_t afr[4][4];
                #pragma unroll
                for (int mi = 0; mi < 4; mi++) {
                    int row = wm * 64 + mi * 16 + ((lane >> 3) & 1) * 8 + (lane & 7);
                    int kofs = ks + ((lane >> 4) << 3);
                    ldmx4(afr[mi], As_u + (row * LDSROW + kofs) * 2);
                }
                #pragma unroll
                for (int p = 0; p < 2; p++) {
                    uint32_t bb[4];
                    int row = wn * 32 + p * 16 + ((lane >> 4) << 3) + (lane & 7);
                    int kofs = ks + (((lane >> 3) & 1) << 3);
                    ldmx4(bb, Bs_u + (row * LDSROW + kofs) * 2);
                    #pragma unroll
                    for (int mi = 0; mi < 4; mi++) {
                        mma16816(acc[mi][2 * p],     afr[mi], bb);
                        mma16816(acc[mi][2 * p + 1], afr[mi], bb + 2);
                    }
                }
            }
        }
        __syncthreads();   // pipeline smem free for epilogue reuse

        // fused epilogue: sparse add (flagged rows), relu, pooled reduce
        float* tilebuf = (float*)dsm;                          // [128][130]
        int*   sbatch  = (int*)(dsm + 3 * STAGE_SF);
        if (tid < 128) {
            int r = tile * 128 + tid;
            sbatch[tid] = (r < n) ? bids[r] : -1;
        }
        #pragma unroll
        for (int h = 0; h < 2; h++) {                          // two 128-col halves
            __syncthreads();
            if ((wn >> 2) == h) {                              // 8 warps per half
                #pragma unroll
                for (int mi = 0; mi < 4; mi++) {
                    int rl0 = wm * 64 + mi * 16 + g;
                    #pragma unroll
                    for (int ni = 0; ni < 4; ni++) {
                        int cl = (wn & 3) * 32 + ni * 8 + 2 * t;   // 0..127
                        int gcol = h * 128 + cl;
                        int ra = tile * 128 + rl0, rb = ra + 8;
                        float v0 = acc[mi][ni][0], v1 = acc[mi][ni][1];
                        float v2 = acc[mi][ni][2], v3 = acc[mi][ni][3];
                        if (ra < n && g_flag[ra]) {
                            float2 s = *(float2*)(g_acc + (size_t)ra * 256 + gcol);
                            v0 += s.x; v1 += s.y;
                        }
                        if (rb < n && g_flag[rb]) {
                            float2 s = *(float2*)(g_acc + (size_t)rb * 256 + gcol);
                            v2 += s.x; v3 += s.y;
                        }
                        tilebuf[rl0 * 130 + cl] = v0;
                        tilebuf[rl0 * 130 + cl + 1] = v1;
                        tilebuf[(rl0 + 8) * 130 + cl] = v2;
                        tilebuf[(rl0 + 8) * 130 + cl + 1] = v3;
                    }
                }
            }
            __syncthreads();
            {
                int col = tid & 127, q = tid >> 7;             // 4 row-groups x 128 cols
                float sum = 0.f; int cur = -1;
                #pragma unroll 8
                for (int rr = q * 32; rr < q * 32 + 32; rr++) {
                    int b = sbatch[rr];
                    if (b != cur) {
                        if (cur >= 0)
                            atomicAdd(&out[cur * 256 + h * 128 + col], sum);
                        sum = 0.f; cur = b;
                    }
                    if (b >= 0) {
                        float v = tilebuf[rr * 130 + col];
                        sum += (v > 0.f ? v : 0.f);
                    }
                }
                if (cur >= 0)
                    atomicAdd(&out[cur * 256 + h * 128 + col], sum);
            }
        }
        __syncthreads();
    }
}

// ---------------- finalize ----------------
__global__ void finalize_kernel(float* out) {
    int e = blockIdx.x * 256 + threadIdx.x;
    if (e < 2048) out[e] = out[e] / g_counts[e >> 8];
}

// ---------------- launch ----------------
extern "C" void kernel_launch(void* const* d_in, const int* in_sizes, int n_in,
                              void* d_out, int out_size) {
    const float* feats = (const float*)d_in[0];
    const float* W1    = (const float*)d_in[1];
    const float* W2    = (const float*)d_in[2];
    const int*   nbr   = (const int*)d_in[3];
    const int*   bids  = (const int*)d_in[4];
    int n = in_sizes[0] / 3;
    float* out = (float*)d_out;

    static int cfg = 0;
    if (!cfg) {
        cudaFuncSetAttribute(gemm_kernel,
                             cudaFuncAttributeMaxDynamicSharedMemorySize, SMEM_SP);
        cudaFuncSetAttribute(self_gemm_kernel,
                             cudaFuncAttributeMaxDynamicSharedMemorySize, SMEM_SF);
        cfg = 1;
    }

    int tiles = (n + 127) / 128;
    prep_kernel<<<64, 256>>>(out, bids, n);
    convw2_kernel<<<dim3(8, 8, 9), dim3(32, 8)>>>(W2);
    layer1_kernel<<<2048, 256>>>(feats, W1, nbr, n);
    zero_rows_kernel<<<dim3(256, 8), 64>>>();
    gemm_kernel<<<dim3(40, 16), 256, SMEM_SP>>>();                    // 8 taps x 2 halves
    self_gemm_kernel<<<tiles, 512, SMEM_SF>>>(n, bids, out);          // self + fused pool
    finalize_kernel<<<8, 256>>>(out);
}

// round 13
// speedup vs baseline: 1.0198x; 1.0198x over previous
#include <cuda_runtime.h>
#include <cuda_fp16.h>
#include <cstdint>

#define NMAX 200000
#define PCAP 65536
#define LDSROW 72              // A rows: 64 K-halves + 8 pad (144B)
#define STAGE_SP 36864         // sparse kernel stage: A + B (128x72x2 each)
#define SMEM_SP (3 * STAGE_SP + 512)
// self kernel: resident B + 2-stage A ring
#define BROW 264               // B rows: 256 K-halves + 8 pad (528B)
#define OFF_B 0                // 128 * 264 * 2 = 67584
#define A_STAGE 18432          // 128 * 72 * 2
#define OFF_A 67584            // 2 stages -> 36864
#define OFF_SB 104448
#define SMEM_SELF 104960

// ---------------- device scratch ----------------
__device__ __half g_h1[(size_t)NMAX * 256];
__device__ float  g_acc[(size_t)NMAX * 256];
__device__ __half g_w2t[9 * 256 * 256];        // W2^T fp16 [k][cout][cin]
__device__ int  g_src[9][PCAP];
__device__ int  g_dst[9][PCAP];
__device__ int  g_cnt[9];
__device__ float g_counts[8];
__device__ unsigned char g_flag[NMAX];

// ---------------- prep (+ batch counting) ----------------
__global__ void prep_kernel(float* out, const int* __restrict__ bids, int n) {
    __shared__ int loc[8];
    if (threadIdx.x < 8) loc[threadIdx.x] = 0;
    __syncthreads();
    int t = blockIdx.x * blockDim.x + threadIdx.x;
    int stride = gridDim.x * blockDim.x;
    for (int i = t; i < 2048; i += stride) out[i] = 0.f;
    for (int i = t; i < NMAX / 4; i += stride) ((int*)g_flag)[i] = 0;
    if (t < 9) g_cnt[t] = 0;
    if (t < 8) g_counts[t] = 0.f;
    for (int i = t; i < n; i += stride) atomicAdd(&loc[bids[i]], 1);
    __syncthreads();
    if (threadIdx.x < 8 && loc[threadIdx.x])
        atomicAdd(&g_counts[threadIdx.x], (float)loc[threadIdx.x]);
}

// ---------------- W2 transpose -> fp16 ----------------
__global__ void convw2_kernel(const float* __restrict__ W2) {
    __shared__ float tile[32][33];
    int k = blockIdx.z;
    int ci0 = blockIdx.x * 32, co0 = blockIdx.y * 32;
    int tx = threadIdx.x, ty = threadIdx.y;
    #pragma unroll
    for (int r = 0; r < 32; r += 8) {
        int ci = ci0 + ty + r;
        tile[ty + r][tx] = W2[(k << 16) + (ci << 8) + co0 + tx];
    }
    __syncthreads();
    #pragma unroll
    for (int r = 0; r < 32; r += 8) {
        int co = co0 + ty + r;
        g_w2t[(k << 16) + (co << 8) + ci0 + tx] = __float2half_rn(tile[tx][ty + r]);
    }
}

// ---------------- layer 1: warp per point ----------------
__global__ void layer1_kernel(const float* __restrict__ feats,
                              const float* __restrict__ W1,
                              const int* __restrict__ nbr, int n) {
    int gw = (blockIdx.x * blockDim.x + threadIdx.x) >> 5;
    int lane = threadIdx.x & 31;
    int nw = (gridDim.x * blockDim.x) >> 5;
    for (int i = gw; i < n; i += nw) {
        int j = -1; float f0 = 0.f, f1 = 0.f, f2 = 0.f;
        if (lane < 9) {
            j = nbr[(size_t)i * 9 + lane];
            if (j >= 0) {
                f0 = feats[(size_t)j * 3 + 0];
                f1 = feats[(size_t)j * 3 + 1];
                f2 = feats[(size_t)j * 3 + 2];
            }
        }
        unsigned vm = __ballot_sync(0xffffffffu, lane < 9 && j >= 0);
        if (lane < 9 && j >= 0 && lane != 4) {
            int pos = atomicAdd(&g_cnt[lane], 1);
            if (pos < PCAP) { g_src[lane][pos] = j; g_dst[lane][pos] = i; }
        }
        if (lane == 0) g_flag[i] = (vm & 0x1EFu) ? 1 : 0;
        float acc[8];
        #pragma unroll
        for (int q = 0; q < 8; q++) acc[q] = 0.f;
        int c0 = lane * 8;
        #pragma unroll
        for (int k = 0; k < 9; k++) {
            if (vm & (1u << k)) {
                float a0 = __shfl_sync(0xffffffffu, f0, k);
                float a1 = __shfl_sync(0xffffffffu, f1, k);
                float a2 = __shfl_sync(0xffffffffu, f2, k);
                const float4* w0 = (const float4*)(W1 + (k * 3 + 0) * 256 + c0);
                const float4* w1 = (const float4*)(W1 + (k * 3 + 1) * 256 + c0);
                const float4* w2 = (const float4*)(W1 + (k * 3 + 2) * 256 + c0);
                float4 x0 = w0[0], x1 = w0[1];
                float4 y0 = w1[0], y1 = w1[1];
                float4 z0 = w2[0], z1 = w2[1];
                acc[0] += a0 * x0.x + a1 * y0.x + a2 * z0.x;
                acc[1] += a0 * x0.y + a1 * y0.y + a2 * z0.y;
                acc[2] += a0 * x0.z + a1 * y0.z + a2 * z0.z;
                acc[3] += a0 * x0.w + a1 * y0.w + a2 * z0.w;
                acc[4] += a0 * x1.x + a1 * y1.x + a2 * z1.x;
                acc[5] += a0 * x1.y + a1 * y1.y + a2 * z1.y;
                acc[6] += a0 * x1.z + a1 * y1.z + a2 * z1.z;
                acc[7] += a0 * x1.w + a1 * y1.w + a2 * z1.w;
            }
        }
        __half2 o[4];
        #pragma unroll
        for (int q = 0; q < 4; q++) {
            float u = acc[2 * q],     v = acc[2 * q + 1];
            o[q] = __floats2half2_rn(u > 0.f ? u : 0.f, v > 0.f ? v : 0.f);
        }
        *(uint4*)(g_h1 + (size_t)i * 256 + c0) = *(uint4*)o;
    }
}

// ---------------- zero g_acc rows right before the sparse scatter ---------
// (placement load-bearing: keeps zeroed lines L2-hot for the atomics)
__global__ void zero_rows_kernel() {
    int tap = blockIdx.y;
    int kk = (tap < 4) ? tap : tap + 1;
    int cnt = g_cnt[kk]; if (cnt > PCAP) cnt = PCAP;
    float4 z = make_float4(0.f, 0.f, 0.f, 0.f);
    for (int p = blockIdx.x; p < cnt; p += gridDim.x) {
        int row = g_dst[kk][p];
        float4* dst = (float4*)(g_acc + (size_t)row * 256);
        for (int e = threadIdx.x; e < 64; e += blockDim.x) dst[e] = z;
    }
}

// ---------------- GEMM helpers ----------------
__device__ __forceinline__ void mma16816(float c[4], const uint32_t a[4],
                                         const uint32_t* b) {
    asm volatile(
        "mma.sync.aligned.m16n8k16.row.col.f32.f16.f16.f32 "
        "{%0,%1,%2,%3}, {%4,%5,%6,%7}, {%8,%9}, {%0,%1,%2,%3};\n"
        : "+f"(c[0]), "+f"(c[1]), "+f"(c[2]), "+f"(c[3])
        : "r"(a[0]), "r"(a[1]), "r"(a[2]), "r"(a[3]), "r"(b[0]), "r"(b[1]));
}
__device__ __forceinline__ void ldmx4(uint32_t* r, uint32_t saddr) {
    asm volatile("ldmatrix.sync.aligned.m8n8.x4.shared.b16 {%0,%1,%2,%3}, [%4];"
                 : "=r"(r[0]), "=r"(r[1]), "=r"(r[2]), "=r"(r[3]) : "r"(saddr));
}
__device__ __forceinline__ void red_v2(float* p, float v0, float v1) {
    asm volatile("red.global.add.v2.f32 [%0], {%1,%2};"
                 :: "l"(p), "f"(v0), "f"(v1) : "memory");
}
__device__ __forceinline__ void cp16(uint32_t saddr, const void* g, bool valid) {
    int sz = valid ? 16 : 0;
    asm volatile("cp.async.cg.shared.global [%0], [%1], 16, %2;"
                 :: "r"(saddr), "l"(g), "r"(sz));
}

// ---------------- sparse GEMM (R11, unchanged): 128Mx128N, KC=64 ----------
__global__ __launch_bounds__(256, 2) void gemm_kernel() {
    extern __shared__ __align__(16) char dsm[];
    uint32_t sbase = (uint32_t)__cvta_generic_to_shared(dsm);
    int tid = threadIdx.x, lane = tid & 31, warp = tid >> 5;
    int wm = warp >> 2, wn = warp & 3;
    int g = lane >> 2, t = lane & 3;

    int y = blockIdx.y;
    int tap = y >> 1, nhalf = y & 1;
    int kk = (tap < 4) ? tap : tap + 1;
    int cnt = g_cnt[kk]; if (cnt > PCAP) cnt = PCAP;
    int tiles = (cnt + 127) >> 7;
    const int* srcl = g_src[kk];
    const int* dstl = g_dst[kk];
    const __half* BW = g_w2t + (size_t)kk * 65536 + (size_t)nhalf * 128 * 256;

    int r_ld = tid >> 3, q_ld = tid & 7;

    for (int tile = blockIdx.x; tile < tiles; tile += gridDim.x) {
        float acc[4][4][4];
        #pragma unroll
        for (int a = 0; a < 4; a++)
            #pragma unroll
            for (int b = 0; b < 4; b++)
                #pragma unroll
                for (int d = 0; d < 4; d++) acc[a][b][d] = 0.f;

        const __half* asrc[4]; bool aval[4];
        #pragma unroll
        for (int i = 0; i < 4; i++) {
            int ar = tile * 128 + r_ld + i * 32;
            aval[i] = (ar < cnt);
            asrc[i] = g_h1 + (size_t)(aval[i] ? srcl[ar] : 0) * 256;
        }

        auto issue = [&](int c) {
            if (c < 4) {
                int kc = c * 64;
                uint32_t sa = sbase + (uint32_t)(c % 3) * STAGE_SP;
                #pragma unroll
                for (int i = 0; i < 4; i++) {
                    int row = r_ld + i * 32;
                    uint32_t da = sa + (row * LDSROW + q_ld * 8) * 2;
                    cp16(da, asrc[i] + kc + q_ld * 8, aval[i]);
                    cp16(da + 18432, BW + row * 256 + kc + q_ld * 8, true);
                }
            }
            asm volatile("cp.async.commit_group;");
        };

        issue(0); issue(1);
        #pragma unroll 1
        for (int c = 0; c < 4; c++) {
            asm volatile("cp.async.wait_group 1;");
            __syncthreads();
            issue(c + 2);
            uint32_t As_u = sbase + (uint32_t)(c % 3) * STAGE_SP;
            uint32_t Bs_u = As_u + 18432;
            #pragma unroll
            for (int ks = 0; ks < 64; ks += 16) {
                uint32_t afr[4][4];
                #pragma unroll
                for (int mi = 0; mi < 4; mi++) {
                    int row = wm * 64 + mi * 16 + ((lane >> 3) & 1) * 8 + (lane & 7);
                    int kofs = ks + ((lane >> 4) << 3);
                    ldmx4(afr[mi], As_u + (row * LDSROW + kofs) * 2);
                }
                #pragma unroll
                for (int p = 0; p < 2; p++) {
                    uint32_t bb[4];
                    int row = wn * 32 + p * 16 + ((lane >> 4) << 3) + (lane & 7);
                    int kofs = ks + (((lane >> 3) & 1) << 3);
                    ldmx4(bb, Bs_u + (row * LDSROW + kofs) * 2);
                    #pragma unroll
                    for (int mi = 0; mi < 4; mi++) {
                        mma16816(acc[mi][2 * p],     afr[mi], bb);
                        mma16816(acc[mi][2 * p + 1], afr[mi], bb + 2);
                    }
                }
            }
        }
        __syncthreads();

        #pragma unroll
        for (int mi = 0; mi < 4; mi++) {
            int rr = wm * 64 + mi * 16 + g;
            #pragma unroll
            for (int ni = 0; ni < 4; ni++) {
                int col = nhalf * 128 + wn * 32 + ni * 8 + 2 * t;
                int ra = tile * 128 + rr, rb = ra + 8;
                if (ra < cnt)
                    red_v2(g_acc + (size_t)dstl[ra] * 256 + col,
                           acc[mi][ni][0], acc[mi][ni][1]);
                if (rb < cnt)
                    red_v2(g_acc + (size_t)dstl[rb] * 256 + col,
                           acc[mi][ni][2], acc[mi][ni][3]);
            }
        }
    }
}

// ---------------- self GEMM: persistent blocks, B resident in smem --------
__global__ __launch_bounds__(256, 2) void self_gemm_kernel(int n,
                                                           const int* __restrict__ bids,
                                                           float* __restrict__ out) {
    extern __shared__ __align__(16) char dsm[];
    uint32_t sbase = (uint32_t)__cvta_generic_to_shared(dsm);
    int tid = threadIdx.x, lane = tid & 31, warp = tid >> 5;
    int wm = warp >> 2, wn = warp & 3;    // warp tile 64M x 32N
    int g = lane >> 2, t = lane & 3;

    int nhalf = blockIdx.x;
    int tiles = (n + 127) >> 7;
    const __half* BW = g_w2t + 4 * 65536 + (size_t)nhalf * 128 * 256;

    int r_ld = tid >> 3, q_ld = tid & 7;   // rows r_ld + 32*i, 8 x 16B slots

    // ---- load B once per block: 128 rows x 256 K-halves, row stride BROW ----
    #pragma unroll
    for (int i = 0; i < 4; i++) {
        int row = r_ld + i * 32;
        #pragma unroll
        for (int kcc = 0; kcc < 4; kcc++)
            cp16(sbase + OFF_B + (row * BROW + kcc * 64 + q_ld * 8) * 2,
                 BW + row * 256 + kcc * 64 + q_ld * 8, true);
    }
    asm volatile("cp.async.commit_group;");
    uint32_t B_u = sbase + OFF_B;

    for (int tile = blockIdx.y; tile < tiles; tile += gridDim.y) {
        float acc[4][4][4];
        #pragma unroll
        for (int a = 0; a < 4; a++)
            #pragma unroll
            for (int b = 0; b < 4; b++)
                #pragma unroll
                for (int d = 0; d < 4; d++) acc[a][b][d] = 0.f;

        const __half* asrc[4]; bool aval[4];
        #pragma unroll
        for (int i = 0; i < 4; i++) {
            int ar = tile * 128 + r_ld + i * 32;
            aval[i] = (ar < n);
            asrc[i] = g_h1 + (size_t)(aval[i] ? ar : 0) * 256;
        }

        auto issueA = [&](int c) {       // A chunk c -> slot c&1
            int kc = c * 64;
            uint32_t sa = sbase + OFF_A + (uint32_t)(c & 1) * A_STAGE;
            #pragma unroll
            for (int i = 0; i < 4; i++) {
                int row = r_ld + i * 32;
                cp16(sa + (row * LDSROW + q_ld * 8) * 2,
                     asrc[i] + kc + q_ld * 8, aval[i]);
            }
            asm volatile("cp.async.commit_group;");
        };

        issueA(0);
        #pragma unroll 1
        for (int c = 0; c < 4; c++) {
            asm volatile("cp.async.wait_group 0;");   // chunk c (and B, first time)
            __syncthreads();
            if (c < 3) issueA(c + 1);
            uint32_t As_u = sbase + OFF_A + (uint32_t)(c & 1) * A_STAGE;
            #pragma unroll
            for (int ks = 0; ks < 64; ks += 16) {
                uint32_t afr[4][4];
                #pragma unroll
                for (int mi = 0; mi < 4; mi++) {
                    int row = wm * 64 + mi * 16 + ((lane >> 3) & 1) * 8 + (lane & 7);
                    int kofs = ks + ((lane >> 4) << 3);
                    ldmx4(afr[mi], As_u + (row * LDSROW + kofs) * 2);
                }
                #pragma unroll
                for (int p = 0; p < 2; p++) {
                    uint32_t bb[4];
                    int row = wn * 32 + p * 16 + ((lane >> 4) << 3) + (lane & 7);
                    int kabs = c * 64 + ks + (((lane >> 3) & 1) << 3);
                    ldmx4(bb, B_u + (row * BROW + kabs) * 2);
                    #pragma unroll
                    for (int mi = 0; mi < 4; mi++) {
                        mma16816(acc[mi][2 * p],     afr[mi], bb);
                        mma16816(acc[mi][2 * p + 1], afr[mi], bb + 2);
                    }
                }
            }
        }
        __syncthreads();   // A-ring smem now free for epilogue tilebuf

        // fused epilogue: sparse add (flagged rows), relu, pooled reduce
        float* tilebuf = (float*)(dsm + OFF_A);               // [128][66] in A ring
        int*   sbatch  = (int*)(dsm + OFF_SB);
        if (tid < 128) {
            int r = tile * 128 + tid;
            sbatch[tid] = (r < n) ? bids[r] : -1;
        }
        #pragma unroll
        for (int h = 0; h < 2; h++) {
            __syncthreads();
            if ((wn >> 1) == h) {
                #pragma unroll
                for (int mi = 0; mi < 4; mi++) {
                    int rl0 = wm * 64 + mi * 16 + g;
                    #pragma unroll
                    for (int ni = 0; ni < 4; ni++) {
                        int cl = (wn & 1) * 32 + ni * 8 + 2 * t;   // 0..63
                        int gcol = nhalf * 128 + h * 64 + cl;
                        int ra = tile * 128 + rl0, rb = ra + 8;
                        float v0 = acc[mi][ni][0], v1 = acc[mi][ni][1];
                        float v2 = acc[mi][ni][2], v3 = acc[mi][ni][3];
                        if (ra < n && g_flag[ra]) {
                            float2 s = *(float2*)(g_acc + (size_t)ra * 256 + gcol);
                            v0 += s.x; v1 += s.y;
                        }
                        if (rb < n && g_flag[rb]) {
                            float2 s = *(float2*)(g_acc + (size_t)rb * 256 + gcol);
                            v2 += s.x; v3 += s.y;
                        }
                        tilebuf[rl0 * 66 + cl] = v0;
                        tilebuf[rl0 * 66 + cl + 1] = v1;
                        tilebuf[(rl0 + 8) * 66 + cl] = v2;
                        tilebuf[(rl0 + 8) * 66 + cl + 1] = v3;
                    }
                }
            }
            __syncthreads();
            {
                int col = tid & 63, q = tid >> 6;          // 4 row-groups x 64 cols
                float sum = 0.f; int cur = -1;
                #pragma unroll 8
                for (int rr = q * 32; rr < q * 32 + 32; rr++) {
                    int b = sbatch[rr];
                    if (b != cur) {
                        if (cur >= 0)
                            atomicAdd(&out[cur * 256 + nhalf * 128 + h * 64 + col], sum);
                        sum = 0.f; cur = b;
                    }
                    if (b >= 0) {
                        float v = tilebuf[rr * 66 + col];
                        sum += (v > 0.f ? v : 0.f);
                    }
                }
                if (cur >= 0)
                    atomicAdd(&out[cur * 256 + nhalf * 128 + h * 64 + col], sum);
            }
        }
        __syncthreads();   // tilebuf region reused as A ring next tile
    }
}

// ---------------- finalize ----------------
__global__ void finalize_kernel(float* out) {
    int e = blockIdx.x * 256 + threadIdx.x;
    if (e < 2048) out[e] = out[e] / g_counts[e >> 8];
}

// ---------------- launch ----------------
extern "C" void kernel_launch(void* const* d_in, const int* in_sizes, int n_in,
                              void* d_out, int out_size) {
    const float* feats = (const float*)d_in[0];
    const float* W1    = (const float*)d_in[1];
    const float* W2    = (const float*)d_in[2];
    const int*   nbr   = (const int*)d_in[3];
    const int*   bids  = (const int*)d_in[4];
    int n = in_sizes[0] / 3;
    float* out = (float*)d_out;

    static int cfg = 0;
    if (!cfg) {
        cudaFuncSetAttribute(gemm_kernel,
                             cudaFuncAttributeMaxDynamicSharedMemorySize, SMEM_SP);
        cudaFuncSetAttribute(self_gemm_kernel,
                             cudaFuncAttributeMaxDynamicSharedMemorySize, SMEM_SELF);
        cfg = 1;
    }

    prep_kernel<<<64, 256>>>(out, bids, n);
    convw2_kernel<<<dim3(8, 8, 9), dim3(32, 8)>>>(W2);
    layer1_kernel<<<2048, 256>>>(feats, W1, nbr, n);
    zero_rows_kernel<<<dim3(256, 8), 64>>>();
    gemm_kernel<<<dim3(40, 16), 256, SMEM_SP>>>();                     // 8 taps x 2 halves
    self_gemm_kernel<<<dim3(2, 152), 256, SMEM_SELF>>>(n, bids, out);  // persistent, B resident
    finalize_kernel<<<8, 256>>>(out);
}

// round 15
// speedup vs baseline: 1.0484x; 1.0280x over previous
#include <cuda_runtime.h>
#include <cuda_fp16.h>
#include <cstdint>

#define NMAX 200000
#define PCAP 65536
#define LDSROW 72              // 64 K-halves + 8 pad (144B rows)
#define STAGE_BYTES 36864      // A 128x72x2 + B 128x72x2
#define SMEM_DYN (3 * STAGE_BYTES + 512)

// ---------------- device scratch ----------------
__device__ __half g_h1[(size_t)NMAX * 256];
__device__ float  g_acc[(size_t)NMAX * 256];
__device__ __half g_w2t[9 * 256 * 256];        // W2^T fp16 [k][cout][cin]
__device__ int  g_src[9][PCAP];
__device__ int  g_dst[9][PCAP];
__device__ int  g_cnt[9];
__device__ float g_counts[8];
__device__ unsigned char g_flag[NMAX];

// ---------------- fused prep + W2 transpose (zero ONLY; no accumulation) --
__global__ void prepconv_kernel(const float* __restrict__ W2, float* out) {
    __shared__ float tile[32][33];
    int tx = threadIdx.x, ty = threadIdx.y;
    int ltid = ty * 32 + tx;

    int bid = blockIdx.x;
    int k = bid / 64, rem = bid % 64;
    int ci0 = (rem & 7) * 32, co0 = (rem >> 3) * 32;
    #pragma unroll
    for (int r = 0; r < 32; r += 8) {
        int ci = ci0 + ty + r;
        tile[ty + r][tx] = W2[(k << 16) + (ci << 8) + co0 + tx];
    }
    __syncthreads();
    #pragma unroll
    for (int r = 0; r < 32; r += 8) {
        int co = co0 + ty + r;
        g_w2t[(k << 16) + (co << 8) + ci0 + tx] = __float2half_rn(tile[tx][ty + r]);
    }

    // prep slice (pure zeroing — all accumulation happens in later kernels)
    int t = bid * 256 + ltid;
    int stride = gridDim.x * 256;
    for (int i = t; i < 2048; i += stride) out[i] = 0.f;
    for (int i = t; i < NMAX / 4; i += stride) ((int*)g_flag)[i] = 0;
    if (t < 9) g_cnt[t] = 0;
    if (t < 8) g_counts[t] = 0.f;
}

// ---------------- layer 1: warp/point + g_acc row zero + batch counting ---
__global__ void layer1_kernel(const float* __restrict__ feats,
                              const float* __restrict__ W1,
                              const int* __restrict__ nbr,
                              const int* __restrict__ bids, int n) {
    __shared__ int loc[8];
    if (threadIdx.x < 8) loc[threadIdx.x] = 0;
    __syncthreads();
    int gw = (blockIdx.x * blockDim.x + threadIdx.x) >> 5;
    int lane = threadIdx.x & 31;
    int nw = (gridDim.x * blockDim.x) >> 5;
    for (int i = gw; i < n; i += nw) {
        int j = -1; float f0 = 0.f, f1 = 0.f, f2 = 0.f;
        if (lane < 9) {
            j = nbr[(size_t)i * 9 + lane];
            if (j >= 0) {
                f0 = feats[(size_t)j * 3 + 0];
                f1 = feats[(size_t)j * 3 + 1];
                f2 = feats[(size_t)j * 3 + 2];
            }
        }
        unsigned vm = __ballot_sync(0xffffffffu, lane < 9 && j >= 0);
        if (lane < 9 && j >= 0 && lane != 4) {
            int pos = atomicAdd(&g_cnt[lane], 1);
            if (pos < PCAP) { g_src[lane][pos] = j; g_dst[lane][pos] = i; }
        }
        bool fl = (vm & 0x1EFu) != 0;
        if (lane == 0) {
            g_flag[i] = fl ? 1 : 0;
            atomicAdd(&loc[bids[i]], 1);
        }
        if (fl) {   // zero this g_acc row (receives sparse atomics next kernel)
            uint4 z = make_uint4(0, 0, 0, 0);
            uint4* dst = (uint4*)(g_acc + (size_t)i * 256 + lane * 8);
            dst[0] = z; dst[1] = z;
        }
        float acc[8];
        #pragma unroll
        for (int q = 0; q < 8; q++) acc[q] = 0.f;
        int c0 = lane * 8;
        #pragma unroll
        for (int k = 0; k < 9; k++) {
            if (vm & (1u << k)) {
                float a0 = __shfl_sync(0xffffffffu, f0, k);
                float a1 = __shfl_sync(0xffffffffu, f1, k);
                float a2 = __shfl_sync(0xffffffffu, f2, k);
                const float4* w0 = (const float4*)(W1 + (k * 3 + 0) * 256 + c0);
                const float4* w1 = (const float4*)(W1 + (k * 3 + 1) * 256 + c0);
                const float4* w2 = (const float4*)(W1 + (k * 3 + 2) * 256 + c0);
                float4 x0 = w0[0], x1 = w0[1];
                float4 y0 = w1[0], y1 = w1[1];
                float4 z0 = w2[0], z1 = w2[1];
                acc[0] += a0 * x0.x + a1 * y0.x + a2 * z0.x;
                acc[1] += a0 * x0.y + a1 * y0.y + a2 * z0.y;
                acc[2] += a0 * x0.z + a1 * y0.z + a2 * z0.z;
                acc[3] += a0 * x0.w + a1 * y0.w + a2 * z0.w;
                acc[4] += a0 * x1.x + a1 * y1.x + a2 * z1.x;
                acc[5] += a0 * x1.y + a1 * y1.y + a2 * z1.y;
                acc[6] += a0 * x1.z + a1 * y1.z + a2 * z1.z;
                acc[7] += a0 * x1.w + a1 * y1.w + a2 * z1.w;
            }
        }
        __half2 o[4];
        #pragma unroll
        for (int q = 0; q < 4; q++) {
            float u = acc[2 * q],     v = acc[2 * q + 1];
            o[q] = __floats2half2_rn(u > 0.f ? u : 0.f, v > 0.f ? v : 0.f);
        }
        *(uint4*)(g_h1 + (size_t)i * 256 + c0) = *(uint4*)o;
    }
    __syncthreads();
    if (threadIdx.x < 8 && loc[threadIdx.x])
        atomicAdd(&g_counts[threadIdx.x], (float)loc[threadIdx.x]);
}

// ---------------- GEMM helpers ----------------
__device__ __forceinline__ void mma16816(float c[4], const uint32_t a[4],
                                         const uint32_t* b) {
    asm volatile(
        "mma.sync.aligned.m16n8k16.row.col.f32.f16.f16.f32 "
        "{%0,%1,%2,%3}, {%4,%5,%6,%7}, {%8,%9}, {%0,%1,%2,%3};\n"
        : "+f"(c[0]), "+f"(c[1]), "+f"(c[2]), "+f"(c[3])
        : "r"(a[0]), "r"(a[1]), "r"(a[2]), "r"(a[3]), "r"(b[0]), "r"(b[1]));
}
__device__ __forceinline__ void ldmx4(uint32_t* r, uint32_t saddr) {
    asm volatile("ldmatrix.sync.aligned.m8n8.x4.shared.b16 {%0,%1,%2,%3}, [%4];"
                 : "=r"(r[0]), "=r"(r[1]), "=r"(r[2]), "=r"(r[3]) : "r"(saddr));
}
__device__ __forceinline__ void red_v2(float* p, float v0, float v1) {
    asm volatile("red.global.add.v2.f32 [%0], {%1,%2};"
                 :: "l"(p), "f"(v0), "f"(v1) : "memory");
}
__device__ __forceinline__ void cp16(uint32_t saddr, const void* g, bool valid) {
    int sz = valid ? 16 : 0;
    asm volatile("cp.async.cg.shared.global [%0], [%1], 16, %2;"
                 :: "r"(saddr), "l"(g), "r"(sz));
}

// ---------------- unified GEMM (R11 form): 128Mx128N, KC=64, 3-stage ------
__global__ __launch_bounds__(256, 2) void gemm_kernel(int n, int self,
                                                      const int* __restrict__ bids,
                                                      float* __restrict__ out) {
    extern __shared__ __align__(16) char dsm[];
    uint32_t sbase = (uint32_t)__cvta_generic_to_shared(dsm);
    int tid = threadIdx.x, lane = tid & 31, warp = tid >> 5;
    int wm = warp >> 2, wn = warp & 3;    // warp tile 64M x 32N
    int g = lane >> 2, t = lane & 3;

    int kk, tiles, cnt = 0, nhalf, tile0, tstep;
    const int* srcl = nullptr; const int* dstl = nullptr;
    if (self) {
        kk = 4; nhalf = blockIdx.x;
        tiles = (n + 127) >> 7;
        tile0 = blockIdx.y; tstep = gridDim.y;
    } else {
        int y = blockIdx.y;
        int tap = y >> 1; nhalf = y & 1;
        kk = (tap < 4) ? tap : tap + 1;
        cnt = g_cnt[kk]; if (cnt > PCAP) cnt = PCAP;
        tiles = (cnt + 127) >> 7;
        srcl = g_src[kk]; dstl = g_dst[kk];
        tile0 = blockIdx.x; tstep = gridDim.x;
    }
    const __half* BW = g_w2t + (size_t)kk * 65536 + (size_t)nhalf * 128 * 256;

    int r_ld = tid >> 3, q_ld = tid & 7;

    for (int tile = tile0; tile < tiles; tile += tstep) {
        float acc[4][4][4];
        #pragma unroll
        for (int a = 0; a < 4; a++)
            #pragma unroll
            for (int b = 0; b < 4; b++)
                #pragma unroll
                for (int d = 0; d < 4; d++) acc[a][b][d] = 0.f;

        const __half* asrc[4]; bool aval[4];
        #pragma unroll
        for (int i = 0; i < 4; i++) {
            int ar = tile * 128 + r_ld + i * 32;
            if (self) {
                aval[i] = (ar < n);
                asrc[i] = g_h1 + (size_t)(aval[i] ? ar : 0) * 256;
            } else {
                aval[i] = (ar < cnt);
                asrc[i] = g_h1 + (size_t)(aval[i] ? srcl[ar] : 0) * 256;
            }
        }

        auto issue = [&](int c) {
            if (c < 4) {
                int kc = c * 64;
                uint32_t sa = sbase + (uint32_t)(c % 3) * STAGE_BYTES;
                #pragma unroll
                for (int i = 0; i < 4; i++) {
                    int row = r_ld + i * 32;
                    uint32_t da = sa + (row * LDSROW + q_ld * 8) * 2;
                    cp16(da, asrc[i] + kc + q_ld * 8, aval[i]);
                    cp16(da + 18432, BW + row * 256 + kc + q_ld * 8, true);
                }
            }
            asm volatile("cp.async.commit_group;");
        };

        issue(0); issue(1);
        #pragma unroll 1
        for (int c = 0; c < 4; c++) {
            asm volatile("cp.async.wait_group 1;");
            __syncthreads();
            issue(c + 2);
            uint32_t As_u = sbase + (uint32_t)(c % 3) * STAGE_BYTES;
            uint32_t Bs_u = As_u + 18432;
            #pragma unroll
            for (int ks = 0; ks < 64; ks += 16) {
                uint32_t afr[4][4];
                #pragma unroll
                for (int mi = 0; mi < 4; mi++) {
                    int row = wm * 64 + mi * 16 + ((lane >> 3) & 1) * 8 + (lane & 7);
                    int kofs = ks + ((lane >> 4) << 3);
                    ldmx4(afr[mi], As_u + (row * LDSROW + kofs) * 2);
                }
                #pragma unroll
                for (int p = 0; p < 2; p++) {
                    uint32_t bb[4];
                    int row = wn * 32 + p * 16 + ((lane >> 4) << 3) + (lane & 7);
                    int kofs = ks + (((lane >> 3) & 1) << 3);
                    ldmx4(bb, Bs_u + (row * LDSROW + kofs) * 2);
                    #pragma unroll
                    for (int mi = 0; mi < 4; mi++) {
                        mma16816(acc[mi][2 * p],     afr[mi], bb);
                        mma16816(acc[mi][2 * p + 1], afr[mi], bb + 2);
                    }
                }
            }
        }
        __syncthreads();

        if (!self) {
            #pragma unroll
            for (int mi = 0; mi < 4; mi++) {
                int rr = wm * 64 + mi * 16 + g;
                #pragma unroll
                for (int ni = 0; ni < 4; ni++) {
                    int col = nhalf * 128 + wn * 32 + ni * 8 + 2 * t;
                    int ra = tile * 128 + rr, rb = ra + 8;
                    if (ra < cnt)
                        red_v2(g_acc + (size_t)dstl[ra] * 256 + col,
                               acc[mi][ni][0], acc[mi][ni][1]);
                    if (rb < cnt)
                        red_v2(g_acc + (size_t)dstl[rb] * 256 + col,
                               acc[mi][ni][2], acc[mi][ni][3]);
                }
            }
        } else {
            float* tilebuf = (float*)dsm;                         // [128][66]
            int*   sbatch  = (int*)(dsm + 3 * STAGE_BYTES);
            if (tid < 128) {
                int r = tile * 128 + tid;
                sbatch[tid] = (r < n) ? bids[r] : -1;
            }
            #pragma unroll
            for (int h = 0; h < 2; h++) {
                __syncthreads();
                if ((wn >> 1) == h) {
                    #pragma unroll
                    for (int mi = 0; mi < 4; mi++) {
                        int rl0 = wm * 64 + mi * 16 + g;
                        #pragma unroll
                        for (int ni = 0; ni < 4; ni++) {
                            int cl = (wn & 1) * 32 + ni * 8 + 2 * t;
                            int gcol = nhalf * 128 + h * 64 + cl;
                            int ra = tile * 128 + rl0, rb = ra + 8;
                            float v0 = acc[mi][ni][0], v1 = acc[mi][ni][1];
                            float v2 = acc[mi][ni][2], v3 = acc[mi][ni][3];
                            if (ra < n && g_flag[ra]) {
                                float2 s = *(float2*)(g_acc + (size_t)ra * 256 + gcol);
                                v0 += s.x; v1 += s.y;
                            }
                            if (rb < n && g_flag[rb]) {
                                float2 s = *(float2*)(g_acc + (size_t)rb * 256 + gcol);
                                v2 += s.x; v3 += s.y;
                            }
                            tilebuf[rl0 * 66 + cl] = v0;
                            tilebuf[rl0 * 66 + cl + 1] = v1;
                            tilebuf[(rl0 + 8) * 66 + cl] = v2;
                            tilebuf[(rl0 + 8) * 66 + cl + 1] = v3;
                        }
                    }
                }
                __syncthreads();
                {
                    int col = tid & 63, q = tid >> 6;
                    float sum = 0.f; int cur = -1;
                    #pragma unroll 8
                    for (int rr = q * 32; rr < q * 32 + 32; rr++) {
                        int b = sbatch[rr];
                        if (b != cur) {
                            if (cur >= 0)
                                atomicAdd(&out[cur * 256 + nhalf * 128 + h * 64 + col], sum);
                            sum = 0.f; cur = b;
                        }
                        if (b >= 0) {
                            float v = tilebuf[rr * 66 + col];
                            sum += (v > 0.f ? v : 0.f);
                        }
                    }
                    if (cur >= 0)
                        atomicAdd(&out[cur * 256 + nhalf * 128 + h * 64 + col], sum);
                }
            }
            __syncthreads();
        }
    }
}

// ---------------- finalize ----------------
__global__ void finalize_kernel(float* out) {
    int e = blockIdx.x * 256 + threadIdx.x;
    if (e < 2048) out[e] = out[e] / g_counts[e >> 8];
}

// ---------------- launch ----------------
extern "C" void kernel_launch(void* const* d_in, const int* in_sizes, int n_in,
                              void* d_out, int out_size) {
    const float* feats = (const float*)d_in[0];
    const float* W1    = (const float*)d_in[1];
    const float* W2    = (const float*)d_in[2];
    const int*   nbr   = (const int*)d_in[3];
    const int*   bids  = (const int*)d_in[4];
    int n = in_sizes[0] / 3;
    float* out = (float*)d_out;

    static int cfg = 0;
    if (!cfg) {
        cudaFuncSetAttribute(gemm_kernel,
                             cudaFuncAttributeMaxDynamicSharedMemorySize, SMEM_DYN);
        cfg = 1;
    }

    int tiles = (n + 127) / 128;
    prepconv_kernel<<<576, dim3(32, 8)>>>(W2, out);                   // 1 (zero only)
    layer1_kernel<<<2048, 256>>>(feats, W1, nbr, bids, n);            // 2 (+zero rows, +counts)
    gemm_kernel<<<dim3(40, 16), 256, SMEM_DYN>>>(n, 0, bids, out);    // 3 sparse
    gemm_kernel<<<dim3(2, tiles), 256, SMEM_DYN>>>(n, 1, bids, out);  // 4 self (ncu slot)
    finalize_kernel<<<8, 256>>>(out);                                 // 5
}

// round 16
// speedup vs baseline: 1.0999x; 1.0492x over previous
#include <cuda_runtime.h>
#include <cuda_fp16.h>
#include <cuda.h>
#include <cstdint>

#define NMAX 200000
#define PCAP 65536
#define LDSROW 72              // sparse kernel rows: 64 K-halves + 8 pad
#define STAGE_BYTES 36864      // sparse stage: A 128x72x2 + B 128x72x2
#define SMEM_DYN (3 * STAGE_BYTES + 512)
// self TMA kernel smem (after 1024-align): 3 stages x (A 16K + B 16K) + mbar + sbatch
#define TSTAGE 32768
#define OFF_MBAR 98304
#define OFF_SB   98368
#define SMEM_TMA (1024 + 98304 + 64 + 512)

// ---------------- device scratch ----------------
__device__ __half g_h1[(size_t)NMAX * 256];
__device__ float  g_acc[(size_t)NMAX * 256];
__device__ __half g_w2t[9 * 256 * 256];        // W2^T fp16 [k][cout][cin]
__device__ int  g_src[9][PCAP];
__device__ int  g_dst[9][PCAP];
__device__ int  g_cnt[9];
__device__ float g_counts[8];
__device__ unsigned char g_flag[NMAX];

// ---------------- fused prep + W2 transpose (zero only) ----------------
__global__ void prepconv_kernel(const float* __restrict__ W2, float* out) {
    __shared__ float tile[32][33];
    int tx = threadIdx.x, ty = threadIdx.y;
    int ltid = ty * 32 + tx;
    int bid = blockIdx.x;
    int k = bid / 64, rem = bid % 64;
    int ci0 = (rem & 7) * 32, co0 = (rem >> 3) * 32;
    #pragma unroll
    for (int r = 0; r < 32; r += 8) {
        int ci = ci0 + ty + r;
        tile[ty + r][tx] = W2[(k << 16) + (ci << 8) + co0 + tx];
    }
    __syncthreads();
    #pragma unroll
    for (int r = 0; r < 32; r += 8) {
        int co = co0 + ty + r;
        g_w2t[(k << 16) + (co << 8) + ci0 + tx] = __float2half_rn(tile[tx][ty + r]);
    }
    int t = bid * 256 + ltid;
    int stride = gridDim.x * 256;
    for (int i = t; i < 2048; i += stride) out[i] = 0.f;
    for (int i = t; i < NMAX / 4; i += stride) ((int*)g_flag)[i] = 0;
    if (t < 9) g_cnt[t] = 0;
    if (t < 8) g_counts[t] = 0.f;
}

// ---------------- layer 1: warp/point + g_acc row zero + batch counting ---
__global__ void layer1_kernel(const float* __restrict__ feats,
                              const float* __restrict__ W1,
                              const int* __restrict__ nbr,
                              const int* __restrict__ bids, int n) {
    __shared__ int loc[8];
    if (threadIdx.x < 8) loc[threadIdx.x] = 0;
    __syncthreads();
    int gw = (blockIdx.x * blockDim.x + threadIdx.x) >> 5;
    int lane = threadIdx.x & 31;
    int nw = (gridDim.x * blockDim.x) >> 5;
    for (int i = gw; i < n; i += nw) {
        int j = -1; float f0 = 0.f, f1 = 0.f, f2 = 0.f;
        if (lane < 9) {
            j = nbr[(size_t)i * 9 + lane];
            if (j >= 0) {
                f0 = feats[(size_t)j * 3 + 0];
                f1 = feats[(size_t)j * 3 + 1];
                f2 = feats[(size_t)j * 3 + 2];
            }
        }
        unsigned vm = __ballot_sync(0xffffffffu, lane < 9 && j >= 0);
        if (lane < 9 && j >= 0 && lane != 4) {
            int pos = atomicAdd(&g_cnt[lane], 1);
            if (pos < PCAP) { g_src[lane][pos] = j; g_dst[lane][pos] = i; }
        }
        bool fl = (vm & 0x1EFu) != 0;
        if (lane == 0) {
            g_flag[i] = fl ? 1 : 0;
            atomicAdd(&loc[bids[i]], 1);
        }
        if (fl) {
            uint4 z = make_uint4(0, 0, 0, 0);
            uint4* dst = (uint4*)(g_acc + (size_t)i * 256 + lane * 8);
            dst[0] = z; dst[1] = z;
        }
        float acc[8];
        #pragma unroll
        for (int q = 0; q < 8; q++) acc[q] = 0.f;
        int c0 = lane * 8;
        #pragma unroll
        for (int k = 0; k < 9; k++) {
            if (vm & (1u << k)) {
                float a0 = __shfl_sync(0xffffffffu, f0, k);
                float a1 = __shfl_sync(0xffffffffu, f1, k);
                float a2 = __shfl_sync(0xffffffffu, f2, k);
                const float4* w0 = (const float4*)(W1 + (k * 3 + 0) * 256 + c0);
                const float4* w1 = (const float4*)(W1 + (k * 3 + 1) * 256 + c0);
                const float4* w2 = (const float4*)(W1 + (k * 3 + 2) * 256 + c0);
                float4 x0 = w0[0], x1 = w0[1];
                float4 y0 = w1[0], y1 = w1[1];
                float4 z0 = w2[0], z1 = w2[1];
                acc[0] += a0 * x0.x + a1 * y0.x + a2 * z0.x;
                acc[1] += a0 * x0.y + a1 * y0.y + a2 * z0.y;
                acc[2] += a0 * x0.z + a1 * y0.z + a2 * z0.z;
                acc[3] += a0 * x0.w + a1 * y0.w + a2 * z0.w;
                acc[4] += a0 * x1.x + a1 * y1.x + a2 * z1.x;
                acc[5] += a0 * x1.y + a1 * y1.y + a2 * z1.y;
                acc[6] += a0 * x1.z + a1 * y1.z + a2 * z1.z;
                acc[7] += a0 * x1.w + a1 * y1.w + a2 * z1.w;
            }
        }
        __half2 o[4];
        #pragma unroll
        for (int q = 0; q < 4; q++) {
            float u = acc[2 * q],     v = acc[2 * q + 1];
            o[q] = __floats2half2_rn(u > 0.f ? u : 0.f, v > 0.f ? v : 0.f);
        }
        *(uint4*)(g_h1 + (size_t)i * 256 + c0) = *(uint4*)o;
    }
    __syncthreads();
    if (threadIdx.x < 8 && loc[threadIdx.x])
        atomicAdd(&g_counts[threadIdx.x], (float)loc[threadIdx.x]);
}

// ---------------- GEMM helpers ----------------
__device__ __forceinline__ void mma16816(float c[4], const uint32_t a[4],
                                         const uint32_t* b) {
    asm volatile(
        "mma.sync.aligned.m16n8k16.row.col.f32.f16.f16.f32 "
        "{%0,%1,%2,%3}, {%4,%5,%6,%7}, {%8,%9}, {%0,%1,%2,%3};\n"
        : "+f"(c[0]), "+f"(c[1]), "+f"(c[2]), "+f"(c[3])
        : "r"(a[0]), "r"(a[1]), "r"(a[2]), "r"(a[3]), "r"(b[0]), "r"(b[1]));
}
__device__ __forceinline__ void ldmx4(uint32_t* r, uint32_t saddr) {
    asm volatile("ldmatrix.sync.aligned.m8n8.x4.shared.b16 {%0,%1,%2,%3}, [%4];"
                 : "=r"(r[0]), "=r"(r[1]), "=r"(r[2]), "=r"(r[3]) : "r"(saddr));
}
__device__ __forceinline__ void red_v2(float* p, float v0, float v1) {
    asm volatile("red.global.add.v2.f32 [%0], {%1,%2};"
                 :: "l"(p), "f"(v0), "f"(v1) : "memory");
}
__device__ __forceinline__ void cp16(uint32_t saddr, const void* g, bool valid) {
    int sz = valid ? 16 : 0;
    asm volatile("cp.async.cg.shared.global [%0], [%1], 16, %2;"
                 :: "r"(saddr), "l"(g), "r"(sz));
}
__device__ __forceinline__ void mbar_waitp(uint32_t mba, int par) {
    asm volatile(
        "{\n\t.reg .pred P;\n\t"
        "WL%=:\n\t"
        "mbarrier.try_wait.parity.acquire.cta.shared::cta.b64 P, [%0], %1, 0x989680;\n\t"
        "@P bra.uni WD%=;\n\t"
        "bra.uni WL%=;\n\t"
        "WD%=:\n\t}"
        :: "r"(mba), "r"(par) : "memory");
}

// ---------------- sparse GEMM (R15 verbatim): 128Mx128N, KC=64, cp.async --
__global__ __launch_bounds__(256, 2) void gemm_kernel() {
    extern __shared__ __align__(16) char dsm[];
    uint32_t sbase = (uint32_t)__cvta_generic_to_shared(dsm);
    int tid = threadIdx.x, lane = tid & 31, warp = tid >> 5;
    int wm = warp >> 2, wn = warp & 3;
    int g = lane >> 2, t = lane & 3;

    int y = blockIdx.y;
    int tap = y >> 1, nhalf = y & 1;
    int kk = (tap < 4) ? tap : tap + 1;
    int cnt = g_cnt[kk]; if (cnt > PCAP) cnt = PCAP;
    int tiles = (cnt + 127) >> 7;
    const int* srcl = g_src[kk];
    const int* dstl = g_dst[kk];
    const __half* BW = g_w2t + (size_t)kk * 65536 + (size_t)nhalf * 128 * 256;

    int r_ld = tid >> 3, q_ld = tid & 7;

    for (int tile = blockIdx.x; tile < tiles; tile += gridDim.x) {
        float acc[4][4][4];
        #pragma unroll
        for (int a = 0; a < 4; a++)
            #pragma unroll
            for (int b = 0; b < 4; b++)
                #pragma unroll
                for (int d = 0; d < 4; d++) acc[a][b][d] = 0.f;

        const __half* asrc[4]; bool aval[4];
        #pragma unroll
        for (int i = 0; i < 4; i++) {
            int ar = tile * 128 + r_ld + i * 32;
            aval[i] = (ar < cnt);
            asrc[i] = g_h1 + (size_t)(aval[i] ? srcl[ar] : 0) * 256;
        }

        auto issue = [&](int c) {
            if (c < 4) {
                int kc = c * 64;
                uint32_t sa = sbase + (uint32_t)(c % 3) * STAGE_BYTES;
                #pragma unroll
                for (int i = 0; i < 4; i++) {
                    int row = r_ld + i * 32;
                    uint32_t da = sa + (row * LDSROW + q_ld * 8) * 2;
                    cp16(da, asrc[i] + kc + q_ld * 8, aval[i]);
                    cp16(da + 18432, BW + row * 256 + kc + q_ld * 8, true);
                }
            }
            asm volatile("cp.async.commit_group;");
        };

        issue(0); issue(1);
        #pragma unroll 1
        for (int c = 0; c < 4; c++) {
            asm volatile("cp.async.wait_group 1;");
            __syncthreads();
            issue(c + 2);
            uint32_t As_u = sbase + (uint32_t)(c % 3) * STAGE_BYTES;
            uint32_t Bs_u = As_u + 18432;
            #pragma unroll
            for (int ks = 0; ks < 64; ks += 16) {
                uint32_t afr[4][4];
                #pragma unroll
                for (int mi = 0; mi < 4; mi++) {
                    int row = wm * 64 + mi * 16 + ((lane >> 3) & 1) * 8 + (lane & 7);
                    int kofs = ks + ((lane >> 4) << 3);
                    ldmx4(afr[mi], As_u + (row * LDSROW + kofs) * 2);
                }
                #pragma unroll
                for (int p = 0; p < 2; p++) {
                    uint32_t bb[4];
                    int row = wn * 32 + p * 16 + ((lane >> 4) << 3) + (lane & 7);
                    int kofs = ks + (((lane >> 3) & 1) << 3);
                    ldmx4(bb, Bs_u + (row * LDSROW + kofs) * 2);
                    #pragma unroll
                    for (int mi = 0; mi < 4; mi++) {
                        mma16816(acc[mi][2 * p],     afr[mi], bb);
                        mma16816(acc[mi][2 * p + 1], afr[mi], bb + 2);
                    }
                }
            }
        }
        __syncthreads();

        #pragma unroll
        for (int mi = 0; mi < 4; mi++) {
            int rr = wm * 64 + mi * 16 + g;
            #pragma unroll
            for (int ni = 0; ni < 4; ni++) {
                int col = nhalf * 128 + wn * 32 + ni * 8 + 2 * t;
                int ra = tile * 128 + rr, rb = ra + 8;
                if (ra < cnt)
                    red_v2(g_acc + (size_t)dstl[ra] * 256 + col,
                           acc[mi][ni][0], acc[mi][ni][1]);
                if (rb < cnt)
                    red_v2(g_acc + (size_t)dstl[rb] * 256 + col,
                           acc[mi][ni][2], acc[mi][ni][3]);
            }
        }
    }
}

// ---------------- self GEMM: TMA-fed, 128Mx128N, KC=64, 3-slot mbar ring --
__global__ __launch_bounds__(256, 2) void self_tma_kernel(
    const __grid_constant__ CUtensorMap mapA,
    const __grid_constant__ CUtensorMap mapB,
    int n, const int* __restrict__ bids, float* __restrict__ out) {
    extern __shared__ __align__(16) char raw[];
    uint32_t s0 = (uint32_t)__cvta_generic_to_shared(raw);
    uint32_t sbase = (s0 + 1023) & ~1023u;      // SW128 needs 1024-aligned tiles
    char* dsm = raw + (sbase - s0);
    int tid = threadIdx.x, lane = tid & 31, warp = tid >> 5;
    int wm = warp >> 2, wn = warp & 3;           // warp tile 64M x 32N
    int g = lane >> 2, t = lane & 3;

    int nhalf = blockIdx.x;
    int tile = blockIdx.y;                        // one tile per block

    if (tid == 0) {
        #pragma unroll
        for (int s = 0; s < 3; s++)
            asm volatile("mbarrier.init.shared.b64 [%0], %1;"
                         :: "r"(sbase + OFF_MBAR + s * 8), "r"(1u) : "memory");
    }
    __syncthreads();

    auto issue = [&](int c) {
        if (c < 4 && tid == 0) {
            uint32_t slot = (uint32_t)(c % 3);
            uint32_t sa  = sbase + slot * TSTAGE;
            uint32_t mba = sbase + OFF_MBAR + slot * 8;
            asm volatile("mbarrier.arrive.expect_tx.shared.b64 _, [%0], %1;"
                         :: "r"(mba), "r"(32768u) : "memory");
            int xc = c * 64;
            int ya = tile * 128, yb = nhalf * 128;
            asm volatile(
                "cp.async.bulk.tensor.2d.shared::cta.global.tile.mbarrier::complete_tx::bytes "
                "[%0], [%1, {%2, %3}], [%4];"
                :: "r"(sa), "l"(&mapA), "r"(xc), "r"(ya), "r"(mba) : "memory");
            asm volatile(
                "cp.async.bulk.tensor.2d.shared::cta.global.tile.mbarrier::complete_tx::bytes "
                "[%0], [%1, {%2, %3}], [%4];"
                :: "r"(sa + 16384u), "l"(&mapB), "r"(xc), "r"(yb), "r"(mba) : "memory");
        }
    };

    float acc[4][4][4];
    #pragma unroll
    for (int a = 0; a < 4; a++)
        #pragma unroll
        for (int b = 0; b < 4; b++)
            #pragma unroll
            for (int d = 0; d < 4; d++) acc[a][b][d] = 0.f;

    issue(0); issue(1);
    #pragma unroll 1
    for (int c = 0; c < 4; c++) {
        int ph = (c == 3) ? 1 : 0;               // slot0 reused once (chunk 3)
        mbar_waitp(sbase + OFF_MBAR + (uint32_t)(c % 3) * 8, ph);
        __syncthreads();                          // all warps done with old slot contents
        issue(c + 2);
        uint32_t As_u = sbase + (uint32_t)(c % 3) * TSTAGE;
        uint32_t Bs_u = As_u + 16384u;
        #pragma unroll
        for (int ks = 0; ks < 64; ks += 16) {
            uint32_t afr[4][4];
            #pragma unroll
            for (int mi = 0; mi < 4; mi++) {
                int row = wm * 64 + mi * 16 + ((lane >> 3) & 1) * 8 + (lane & 7);
                int kofs = ks + ((lane >> 4) << 3);
                uint32_t byte = (uint32_t)(row * 128 + kofs * 2);
                ldmx4(afr[mi], As_u + (byte ^ ((byte >> 3) & 0x70)));
            }
            #pragma unroll
            for (int p = 0; p < 2; p++) {
                uint32_t bb[4];
                int row = wn * 32 + p * 16 + ((lane >> 4) << 3) + (lane & 7);
                int kofs = ks + (((lane >> 3) & 1) << 3);
                uint32_t byte = (uint32_t)(row * 128 + kofs * 2);
                ldmx4(bb, Bs_u + (byte ^ ((byte >> 3) & 0x70)));
                #pragma unroll
                for (int mi = 0; mi < 4; mi++) {
                    mma16816(acc[mi][2 * p],     afr[mi], bb);
                    mma16816(acc[mi][2 * p + 1], afr[mi], bb + 2);
                }
            }
        }
    }
    __syncthreads();   // stages fully consumed; smem reused for epilogue

    // fused epilogue: sparse add (flagged rows), relu, pooled reduce
    float* tilebuf = (float*)dsm;                 // [128][66] overlays stages
    int*   sbatch  = (int*)(dsm + OFF_SB);
    if (tid < 128) {
        int r = tile * 128 + tid;
        sbatch[tid] = (r < n) ? bids[r] : -1;
    }
    #pragma unroll
    for (int h = 0; h < 2; h++) {
        __syncthreads();
        if ((wn >> 1) == h) {
            #pragma unroll
            for (int mi = 0; mi < 4; mi++) {
                int rl0 = wm * 64 + mi * 16 + g;
                #pragma unroll
                for (int ni = 0; ni < 4; ni++) {
                    int cl = (wn & 1) * 32 + ni * 8 + 2 * t;
                    int gcol = nhalf * 128 + h * 64 + cl;
                    int ra = tile * 128 + rl0, rb = ra + 8;
                    float v0 = acc[mi][ni][0], v1 = acc[mi][ni][1];
                    float v2 = acc[mi][ni][2], v3 = acc[mi][ni][3];
                    if (ra < n && g_flag[ra]) {
                        float2 s = *(float2*)(g_acc + (size_t)ra * 256 + gcol);
                        v0 += s.x; v1 += s.y;
                    }
                    if (rb < n && g_flag[rb]) {
                        float2 s = *(float2*)(g_acc + (size_t)rb * 256 + gcol);
                        v2 += s.x; v3 += s.y;
                    }
                    tilebuf[rl0 * 66 + cl] = v0;
                    tilebuf[rl0 * 66 + cl + 1] = v1;
                    tilebuf[(rl0 + 8) * 66 + cl] = v2;
                    tilebuf[(rl0 + 8) * 66 + cl + 1] = v3;
                }
            }
        }
        __syncthreads();
        {
            int col = tid & 63, q = tid >> 6;
            float sum = 0.f; int cur = -1;
            #pragma unroll 8
            for (int rr = q * 32; rr < q * 32 + 32; rr++) {
                int b = sbatch[rr];
                if (b != cur) {
                    if (cur >= 0)
                        atomicAdd(&out[cur * 256 + nhalf * 128 + h * 64 + col], sum);
                    sum = 0.f; cur = b;
                }
                if (b >= 0) {
                    float v = tilebuf[rr * 66 + col];
                    sum += (v > 0.f ? v : 0.f);
                }
            }
            if (cur >= 0)
                atomicAdd(&out[cur * 256 + nhalf * 128 + h * 64 + col], sum);
        }
    }
}

// ---------------- finalize ----------------
__global__ void finalize_kernel(float* out) {
    int e = blockIdx.x * 256 + threadIdx.x;
    if (e < 2048) out[e] = out[e] / g_counts[e >> 8];
}

// ---------------- launch ----------------
extern "C" void kernel_launch(void* const* d_in, const int* in_sizes, int n_in,
                              void* d_out, int out_size) {
    const float* feats = (const float*)d_in[0];
    const float* W1    = (const float*)d_in[1];
    const float* W2    = (const float*)d_in[2];
    const int*   nbr   = (const int*)d_in[3];
    const int*   bids  = (const int*)d_in[4];
    int n = in_sizes[0] / 3;
    float* out = (float*)d_out;

    static CUtensorMap s_mapA, s_mapB;
    static int cfg = 0;
    if (!cfg) {
        cudaFuncSetAttribute(gemm_kernel,
                             cudaFuncAttributeMaxDynamicSharedMemorySize, SMEM_DYN);
        cudaFuncSetAttribute(self_tma_kernel,
                             cudaFuncAttributeMaxDynamicSharedMemorySize, SMEM_TMA);
        void* pA = nullptr; cudaGetSymbolAddress(&pA, g_h1);
        void* pB = nullptr; cudaGetSymbolAddress(&pB, g_w2t);
        typedef CUresult (*EncFn)(CUtensorMap*, CUtensorMapDataType, cuuint32_t, void*,
            const cuuint64_t*, const cuuint64_t*, const cuuint32_t*, const cuuint32_t*,
            CUtensorMapInterleave, CUtensorMapSwizzle, CUtensorMapL2promotion,
            CUtensorMapFloatOOBfill);
        EncFn enc = nullptr;
        cudaDriverEntryPointQueryResult qr;
        cudaGetDriverEntryPoint("cuTensorMapEncodeTiled", (void**)&enc,
                                cudaEnableDefault, &qr);
        cuuint64_t dimsA[2] = {256, (cuuint64_t)NMAX};
        cuuint64_t strA[1]  = {512};
        cuuint32_t box[2]   = {64, 128};
        cuuint32_t es[2]    = {1, 1};
        enc(&s_mapA, CU_TENSOR_MAP_DATA_TYPE_UINT16, 2, pA, dimsA, strA, box, es,
            CU_TENSOR_MAP_INTERLEAVE_NONE, CU_TENSOR_MAP_SWIZZLE_128B,
            CU_TENSOR_MAP_L2_PROMOTION_L2_128B, CU_TENSOR_MAP_FLOAT_OOB_FILL_NONE);
        cuuint64_t dimsB[2] = {256, 256};
        void* pB4 = (char*)pB + (size_t)4 * 65536 * 2;   // tap 4 slice
        enc(&s_mapB, CU_TENSOR_MAP_DATA_TYPE_UINT16, 2, pB4, dimsB, strA, box, es,
            CU_TENSOR_MAP_INTERLEAVE_NONE, CU_TENSOR_MAP_SWIZZLE_128B,
            CU_TENSOR_MAP_L2_PROMOTION_L2_128B, CU_TENSOR_MAP_FLOAT_OOB_FILL_NONE);
        cfg = 1;
    }

    int tiles = (n + 127) / 128;
    prepconv_kernel<<<576, dim3(32, 8)>>>(W2, out);                      // 1
    layer1_kernel<<<2048, 256>>>(feats, W1, nbr, bids, n);               // 2
    gemm_kernel<<<dim3(40, 16), 256, SMEM_DYN>>>();                      // 3 sparse
    self_tma_kernel<<<dim3(2, tiles), 256, SMEM_TMA>>>(s_mapA, s_mapB,
                                                       n, bids, out);    // 4 self (ncu)
    finalize_kernel<<<8, 256>>>(out);                                    // 5
}

// round 17
// speedup vs baseline: 1.2734x; 1.1577x over previous
#include <cuda_runtime.h>
#include <cuda_fp16.h>
#include <cuda.h>
#include <cstdint>

#define NMAX 200000
#define PCAP 65536
#define LDSROW 72              // sparse kernel rows: 64 K-halves + 8 pad
#define STAGE_BYTES 36864      // sparse stage: A 128x72x2 + B 128x72x2
#define SMEM_DYN (3 * STAGE_BYTES + 512)
// self TMA kernel: 3 stages x (A 8K + B 16K), no padding (TMA SW128 layout)
#define TSTAGE 24576
#define OFF_MBAR 73728
#define OFF_SB   73792
#define SMEM_TMA (1024 + 73728 + 64 + 256)

// ---------------- device scratch ----------------
__device__ __half g_h1[(size_t)NMAX * 256];
__device__ float  g_acc[(size_t)NMAX * 256];
__device__ __half g_w2t[9 * 256 * 256];        // W2^T fp16 [k][cout][cin]
__device__ int  g_src[9][PCAP];
__device__ int  g_dst[9][PCAP];
__device__ int  g_cnt[9];
__device__ float g_counts[8];
__device__ unsigned char g_flag[NMAX];

// ---------------- fused prep + W2 transpose (zero only) ----------------
__global__ void prepconv_kernel(const float* __restrict__ W2, float* out) {
    __shared__ float tile[32][33];
    int tx = threadIdx.x, ty = threadIdx.y;
    int ltid = ty * 32 + tx;
    int bid = blockIdx.x;
    int k = bid / 64, rem = bid % 64;
    int ci0 = (rem & 7) * 32, co0 = (rem >> 3) * 32;
    #pragma unroll
    for (int r = 0; r < 32; r += 8) {
        int ci = ci0 + ty + r;
        tile[ty + r][tx] = W2[(k << 16) + (ci << 8) + co0 + tx];
    }
    __syncthreads();
    #pragma unroll
    for (int r = 0; r < 32; r += 8) {
        int co = co0 + ty + r;
        g_w2t[(k << 16) + (co << 8) + ci0 + tx] = __float2half_rn(tile[tx][ty + r]);
    }
    int t = bid * 256 + ltid;
    int stride = gridDim.x * 256;
    for (int i = t; i < 2048; i += stride) out[i] = 0.f;
    for (int i = t; i < NMAX / 4; i += stride) ((int*)g_flag)[i] = 0;
    if (t < 9) g_cnt[t] = 0;
    if (t < 8) g_counts[t] = 0.f;
}

// ---------------- layer 1: warp/point + g_acc row zero + batch counting ---
__global__ void layer1_kernel(const float* __restrict__ feats,
                              const float* __restrict__ W1,
                              const int* __restrict__ nbr,
                              const int* __restrict__ bids, int n) {
    __shared__ int loc[8];
    if (threadIdx.x < 8) loc[threadIdx.x] = 0;
    __syncthreads();
    int gw = (blockIdx.x * blockDim.x + threadIdx.x) >> 5;
    int lane = threadIdx.x & 31;
    int nw = (gridDim.x * blockDim.x) >> 5;
    for (int i = gw; i < n; i += nw) {
        int j = -1; float f0 = 0.f, f1 = 0.f, f2 = 0.f;
        if (lane < 9) {
            j = nbr[(size_t)i * 9 + lane];
            if (j >= 0) {
                f0 = feats[(size_t)j * 3 + 0];
                f1 = feats[(size_t)j * 3 + 1];
                f2 = feats[(size_t)j * 3 + 2];
            }
        }
        unsigned vm = __ballot_sync(0xffffffffu, lane < 9 && j >= 0);
        if (lane < 9 && j >= 0 && lane != 4) {
            int pos = atomicAdd(&g_cnt[lane], 1);
            if (pos < PCAP) { g_src[lane][pos] = j; g_dst[lane][pos] = i; }
        }
        bool fl = (vm & 0x1EFu) != 0;
        if (lane == 0) {
            g_flag[i] = fl ? 1 : 0;
            atomicAdd(&loc[bids[i]], 1);
        }
        if (fl) {
            uint4 z = make_uint4(0, 0, 0, 0);
            uint4* dst = (uint4*)(g_acc + (size_t)i * 256 + lane * 8);
            dst[0] = z; dst[1] = z;
        }
        float acc[8];
        #pragma unroll
        for (int q = 0; q < 8; q++) acc[q] = 0.f;
        int c0 = lane * 8;
        #pragma unroll
        for (int k = 0; k < 9; k++) {
            if (vm & (1u << k)) {
                float a0 = __shfl_sync(0xffffffffu, f0, k);
                float a1 = __shfl_sync(0xffffffffu, f1, k);
                float a2 = __shfl_sync(0xffffffffu, f2, k);
                const float4* w0 = (const float4*)(W1 + (k * 3 + 0) * 256 + c0);
                const float4* w1 = (const float4*)(W1 + (k * 3 + 1) * 256 + c0);
                const float4* w2 = (const float4*)(W1 + (k * 3 + 2) * 256 + c0);
                float4 x0 = w0[0], x1 = w0[1];
                float4 y0 = w1[0], y1 = w1[1];
                float4 z0 = w2[0], z1 = w2[1];
                acc[0] += a0 * x0.x + a1 * y0.x + a2 * z0.x;
                acc[1] += a0 * x0.y + a1 * y0.y + a2 * z0.y;
                acc[2] += a0 * x0.z + a1 * y0.z + a2 * z0.z;
                acc[3] += a0 * x0.w + a1 * y0.w + a2 * z0.w;
                acc[4] += a0 * x1.x + a1 * y1.x + a2 * z1.x;
                acc[5] += a0 * x1.y + a1 * y1.y + a2 * z1.y;
                acc[6] += a0 * x1.z + a1 * y1.z + a2 * z1.z;
                acc[7] += a0 * x1.w + a1 * y1.w + a2 * z1.w;
            }
        }
        __half2 o[4];
        #pragma unroll
        for (int q = 0; q < 4; q++) {
            float u = acc[2 * q],     v = acc[2 * q + 1];
            o[q] = __floats2half2_rn(u > 0.f ? u : 0.f, v > 0.f ? v : 0.f);
        }
        *(uint4*)(g_h1 + (size_t)i * 256 + c0) = *(uint4*)o;
    }
    __syncthreads();
    if (threadIdx.x < 8 && loc[threadIdx.x])
        atomicAdd(&g_counts[threadIdx.x], (float)loc[threadIdx.x]);
}

// ---------------- GEMM helpers ----------------
__device__ __forceinline__ void mma16816(float c[4], const uint32_t a[4],
                                         const uint32_t* b) {
    asm volatile(
        "mma.sync.aligned.m16n8k16.row.col.f32.f16.f16.f32 "
        "{%0,%1,%2,%3}, {%4,%5,%6,%7}, {%8,%9}, {%0,%1,%2,%3};\n"
        : "+f"(c[0]), "+f"(c[1]), "+f"(c[2]), "+f"(c[3])
        : "r"(a[0]), "r"(a[1]), "r"(a[2]), "r"(a[3]), "r"(b[0]), "r"(b[1]));
}
__device__ __forceinline__ void ldmx4(uint32_t* r, uint32_t saddr) {
    asm volatile("ldmatrix.sync.aligned.m8n8.x4.shared.b16 {%0,%1,%2,%3}, [%4];"
                 : "=r"(r[0]), "=r"(r[1]), "=r"(r[2]), "=r"(r[3]) : "r"(saddr));
}
__device__ __forceinline__ void red_v2(float* p, float v0, float v1) {
    asm volatile("red.global.add.v2.f32 [%0], {%1,%2};"
                 :: "l"(p), "f"(v0), "f"(v1) : "memory");
}
__device__ __forceinline__ void cp16(uint32_t saddr, const void* g, bool valid) {
    int sz = valid ? 16 : 0;
    asm volatile("cp.async.cg.shared.global [%0], [%1], 16, %2;"
                 :: "r"(saddr), "l"(g), "r"(sz));
}
__device__ __forceinline__ void mbar_waitp(uint32_t mba, int par) {
    asm volatile(
        "{\n\t.reg .pred P;\n\t"
        "WL%=:\n\t"
        "mbarrier.try_wait.parity.acquire.cta.shared::cta.b64 P, [%0], %1, 0x989680;\n\t"
        "@P bra.uni WD%=;\n\t"
        "bra.uni WL%=;\n\t"
        "WD%=:\n\t}"
        :: "r"(mba), "r"(par) : "memory");
}

// ---------------- sparse GEMM (unchanged): 128Mx128N, KC=64, cp.async -----
__global__ __launch_bounds__(256, 2) void gemm_kernel() {
    extern __shared__ __align__(16) char dsm[];
    uint32_t sbase = (uint32_t)__cvta_generic_to_shared(dsm);
    int tid = threadIdx.x, lane = tid & 31, warp = tid >> 5;
    int wm = warp >> 2, wn = warp & 3;
    int g = lane >> 2, t = lane & 3;

    int y = blockIdx.y;
    int tap = y >> 1, nhalf = y & 1;
    int kk = (tap < 4) ? tap : tap + 1;
    int cnt = g_cnt[kk]; if (cnt > PCAP) cnt = PCAP;
    int tiles = (cnt + 127) >> 7;
    const int* srcl = g_src[kk];
    const int* dstl = g_dst[kk];
    const __half* BW = g_w2t + (size_t)kk * 65536 + (size_t)nhalf * 128 * 256;

    int r_ld = tid >> 3, q_ld = tid & 7;

    for (int tile = blockIdx.x; tile < tiles; tile += gridDim.x) {
        float acc[4][4][4];
        #pragma unroll
        for (int a = 0; a < 4; a++)
            #pragma unroll
            for (int b = 0; b < 4; b++)
                #pragma unroll
                for (int d = 0; d < 4; d++) acc[a][b][d] = 0.f;

        const __half* asrc[4]; bool aval[4];
        #pragma unroll
        for (int i = 0; i < 4; i++) {
            int ar = tile * 128 + r_ld + i * 32;
            aval[i] = (ar < cnt);
            asrc[i] = g_h1 + (size_t)(aval[i] ? srcl[ar] : 0) * 256;
        }

        auto issue = [&](int c) {
            if (c < 4) {
                int kc = c * 64;
                uint32_t sa = sbase + (uint32_t)(c % 3) * STAGE_BYTES;
                #pragma unroll
                for (int i = 0; i < 4; i++) {
                    int row = r_ld + i * 32;
                    uint32_t da = sa + (row * LDSROW + q_ld * 8) * 2;
                    cp16(da, asrc[i] + kc + q_ld * 8, aval[i]);
                    cp16(da + 18432, BW + row * 256 + kc + q_ld * 8, true);
                }
            }
            asm volatile("cp.async.commit_group;");
        };

        issue(0); issue(1);
        #pragma unroll 1
        for (int c = 0; c < 4; c++) {
            asm volatile("cp.async.wait_group 1;");
            __syncthreads();
            issue(c + 2);
            uint32_t As_u = sbase + (uint32_t)(c % 3) * STAGE_BYTES;
            uint32_t Bs_u = As_u + 18432;
            #pragma unroll
            for (int ks = 0; ks < 64; ks += 16) {
                uint32_t afr[4][4];
                #pragma unroll
                for (int mi = 0; mi < 4; mi++) {
                    int row = wm * 64 + mi * 16 + ((lane >> 3) & 1) * 8 + (lane & 7);
                    int kofs = ks + ((lane >> 4) << 3);
                    ldmx4(afr[mi], As_u + (row * LDSROW + kofs) * 2);
                }
                #pragma unroll
                for (int p = 0; p < 2; p++) {
                    uint32_t bb[4];
                    int row = wn * 32 + p * 16 + ((lane >> 4) << 3) + (lane & 7);
                    int kofs = ks + (((lane >> 3) & 1) << 3);
                    ldmx4(bb, Bs_u + (row * LDSROW + kofs) * 2);
                    #pragma unroll
                    for (int mi = 0; mi < 4; mi++) {
                        mma16816(acc[mi][2 * p],     afr[mi], bb);
                        mma16816(acc[mi][2 * p + 1], afr[mi], bb + 2);
                    }
                }
            }
        }
        __syncthreads();

        #pragma unroll
        for (int mi = 0; mi < 4; mi++) {
            int rr = wm * 64 + mi * 16 + g;
            #pragma unroll
            for (int ni = 0; ni < 4; ni++) {
                int col = nhalf * 128 + wn * 32 + ni * 8 + 2 * t;
                int ra = tile * 128 + rr, rb = ra + 8;
                if (ra < cnt)
                    red_v2(g_acc + (size_t)dstl[ra] * 256 + col,
                           acc[mi][ni][0], acc[mi][ni][1]);
                if (rb < cnt)
                    red_v2(g_acc + (size_t)dstl[rb] * 256 + col,
                           acc[mi][ni][2], acc[mi][ni][3]);
            }
        }
    }
}

// ---------------- self GEMM: TMA, 64Mx128N tile, 3 blocks/SM --------------
__global__ __launch_bounds__(256, 3) void self_tma_kernel(
    const __grid_constant__ CUtensorMap mapA,
    const __grid_constant__ CUtensorMap mapB,
    int n, const int* __restrict__ bids, float* __restrict__ out) {
    extern __shared__ __align__(16) char raw[];
    uint32_t s0 = (uint32_t)__cvta_generic_to_shared(raw);
    uint32_t sbase = (s0 + 1023) & ~1023u;
    char* dsm = raw + (sbase - s0);
    int tid = threadIdx.x, lane = tid & 31, warp = tid >> 5;
    int wm = warp >> 2, wn = warp & 3;      // warp tile 32M x 32N
    int g = lane >> 2, t = lane & 3;

    int nhalf = blockIdx.x;
    int tile = blockIdx.y;                   // 64-row M tile

    if (tid == 0) {
        #pragma unroll
        for (int s = 0; s < 3; s++)
            asm volatile("mbarrier.init.shared.b64 [%0], %1;"
                         :: "r"(sbase + OFF_MBAR + s * 8), "r"(1u) : "memory");
    }
    __syncthreads();

    auto issue = [&](int c) {
        if (c < 4 && tid == 0) {
            uint32_t slot = (uint32_t)(c % 3);
            uint32_t sa  = sbase + slot * TSTAGE;
            uint32_t mba = sbase + OFF_MBAR + slot * 8;
            asm volatile("mbarrier.arrive.expect_tx.shared.b64 _, [%0], %1;"
                         :: "r"(mba), "r"(24576u) : "memory");
            int xc = c * 64;
            int ya = tile * 64, yb = nhalf * 128;
            asm volatile(
                "cp.async.bulk.tensor.2d.shared::cta.global.tile.mbarrier::complete_tx::bytes "
                "[%0], [%1, {%2, %3}], [%4];"
                :: "r"(sa), "l"(&mapA), "r"(xc), "r"(ya), "r"(mba) : "memory");
            asm volatile(
                "cp.async.bulk.tensor.2d.shared::cta.global.tile.mbarrier::complete_tx::bytes "
                "[%0], [%1, {%2, %3}], [%4];"
                :: "r"(sa + 8192u), "l"(&mapB), "r"(xc), "r"(yb), "r"(mba) : "memory");
        }
    };

    float acc[2][4][4];
    #pragma unroll
    for (int a = 0; a < 2; a++)
        #pragma unroll
        for (int b = 0; b < 4; b++)
            #pragma unroll
            for (int d = 0; d < 4; d++) acc[a][b][d] = 0.f;

    issue(0); issue(1);
    #pragma unroll 1
    for (int c = 0; c < 4; c++) {
        int ph = (c == 3) ? 1 : 0;
        mbar_waitp(sbase + OFF_MBAR + (uint32_t)(c % 3) * 8, ph);
        __syncthreads();
        issue(c + 2);
        uint32_t As_u = sbase + (uint32_t)(c % 3) * TSTAGE;
        uint32_t Bs_u = As_u + 8192u;
        #pragma unroll
        for (int ks = 0; ks < 64; ks += 16) {
            uint32_t afr[2][4];
            #pragma unroll
            for (int mi = 0; mi < 2; mi++) {
                int row = wm * 32 + mi * 16 + ((lane >> 3) & 1) * 8 + (lane & 7);
                int kofs = ks + ((lane >> 4) << 3);
                uint32_t byte = (uint32_t)(row * 128 + kofs * 2);
                ldmx4(afr[mi], As_u + (byte ^ ((byte >> 3) & 0x70)));
            }
            #pragma unroll
            for (int p = 0; p < 2; p++) {
                uint32_t bb[4];
                int row = wn * 32 + p * 16 + ((lane >> 4) << 3) + (lane & 7);
                int kofs = ks + (((lane >> 3) & 1) << 3);
                uint32_t byte = (uint32_t)(row * 128 + kofs * 2);
                ldmx4(bb, Bs_u + (byte ^ ((byte >> 3) & 0x70)));
                #pragma unroll
                for (int mi = 0; mi < 2; mi++) {
                    mma16816(acc[mi][2 * p],     afr[mi], bb);
                    mma16816(acc[mi][2 * p + 1], afr[mi], bb + 2);
                }
            }
        }
    }
    __syncthreads();   // stages consumed; smem reused for epilogue

    // fused epilogue: sparse add (flagged rows), relu, pooled reduce
    float* tilebuf = (float*)dsm;               // [64][66]
    int*   sbatch  = (int*)(dsm + OFF_SB);
    if (tid < 64) {
        int r = tile * 64 + tid;
        sbatch[tid] = (r < n) ? bids[r] : -1;
    }
    #pragma unroll
    for (int h = 0; h < 2; h++) {
        __syncthreads();
        if ((wn >> 1) == h) {
            #pragma unroll
            for (int mi = 0; mi < 2; mi++) {
                int rl0 = wm * 32 + mi * 16 + g;
                #pragma unroll
                for (int ni = 0; ni < 4; ni++) {
                    int cl = (wn & 1) * 32 + ni * 8 + 2 * t;
                    int gcol = nhalf * 128 + h * 64 + cl;
                    int ra = tile * 64 + rl0, rb = ra + 8;
                    float v0 = acc[mi][ni][0], v1 = acc[mi][ni][1];
                    float v2 = acc[mi][ni][2], v3 = acc[mi][ni][3];
                    if (ra < n && g_flag[ra]) {
                        float2 s = *(float2*)(g_acc + (size_t)ra * 256 + gcol);
                        v0 += s.x; v1 += s.y;
                    }
                    if (rb < n && g_flag[rb]) {
                        float2 s = *(float2*)(g_acc + (size_t)rb * 256 + gcol);
                        v2 += s.x; v3 += s.y;
                    }
                    tilebuf[rl0 * 66 + cl] = v0;
                    tilebuf[rl0 * 66 + cl + 1] = v1;
                    tilebuf[(rl0 + 8) * 66 + cl] = v2;
                    tilebuf[(rl0 + 8) * 66 + cl + 1] = v3;
                }
            }
        }
        __syncthreads();
        {
            int col = tid & 63, q = tid >> 6;   // 4 row-groups x 16 rows
            float sum = 0.f; int cur = -1;
            #pragma unroll 8
            for (int rr = q * 16; rr < q * 16 + 16; rr++) {
                int b = sbatch[rr];
                if (b != cur) {
                    if (cur >= 0)
                        atomicAdd(&out[cur * 256 + nhalf * 128 + h * 64 + col], sum);
                    sum = 0.f; cur = b;
                }
                if (b >= 0) {
                    float v = tilebuf[rr * 66 + col];
                    sum += (v > 0.f ? v : 0.f);
                }
            }
            if (cur >= 0)
                atomicAdd(&out[cur * 256 + nhalf * 128 + h * 64 + col], sum);
        }
    }
}

// ---------------- finalize ----------------
__global__ void finalize_kernel(float* out) {
    int e = blockIdx.x * 256 + threadIdx.x;
    if (e < 2048) out[e] = out[e] / g_counts[e >> 8];
}

// ---------------- launch ----------------
extern "C" void kernel_launch(void* const* d_in, const int* in_sizes, int n_in,
                              void* d_out, int out_size) {
    const float* feats = (const float*)d_in[0];
    const float* W1    = (const float*)d_in[1];
    const float* W2    = (const float*)d_in[2];
    const int*   nbr   = (const int*)d_in[3];
    const int*   bids  = (const int*)d_in[4];
    int n = in_sizes[0] / 3;
    float* out = (float*)d_out;

    static CUtensorMap s_mapA, s_mapB;
    static int cfg = 0;
    if (!cfg) {
        cudaFuncSetAttribute(gemm_kernel,
                             cudaFuncAttributeMaxDynamicSharedMemorySize, SMEM_DYN);
        cudaFuncSetAttribute(self_tma_kernel,
                             cudaFuncAttributeMaxDynamicSharedMemorySize, SMEM_TMA);
        void* pA = nullptr; cudaGetSymbolAddress(&pA, g_h1);
        void* pB = nullptr; cudaGetSymbolAddress(&pB, g_w2t);
        typedef CUresult (*EncFn)(CUtensorMap*, CUtensorMapDataType, cuuint32_t, void*,
            const cuuint64_t*, const cuuint64_t*, const cuuint32_t*, const cuuint32_t*,
            CUtensorMapInterleave, CUtensorMapSwizzle, CUtensorMapL2promotion,
            CUtensorMapFloatOOBfill);
        EncFn enc = nullptr;
        cudaDriverEntryPointQueryResult qr;
        cudaGetDriverEntryPoint("cuTensorMapEncodeTiled", (void**)&enc,
                                cudaEnableDefault, &qr);
        cuuint64_t dimsA[2] = {256, (cuuint64_t)NMAX};
        cuuint64_t strA[1]  = {512};
        cuuint32_t boxA[2]  = {64, 64};
        cuuint32_t es[2]    = {1, 1};
        enc(&s_mapA, CU_TENSOR_MAP_DATA_TYPE_UINT16, 2, pA, dimsA, strA, boxA, es,
            CU_TENSOR_MAP_INTERLEAVE_NONE, CU_TENSOR_MAP_SWIZZLE_128B,
            CU_TENSOR_MAP_L2_PROMOTION_L2_128B, CU_TENSOR_MAP_FLOAT_OOB_FILL_NONE);
        cuuint64_t dimsB[2] = {256, 256};
        cuuint32_t boxB[2]  = {64, 128};
        void* pB4 = (char*)pB + (size_t)4 * 65536 * 2;   // tap 4 slice
        enc(&s_mapB, CU_TENSOR_MAP_DATA_TYPE_UINT16, 2, pB4, dimsB, strA, boxB, es,
            CU_TENSOR_MAP_INTERLEAVE_NONE, CU_TENSOR_MAP_SWIZZLE_128B,
            CU_TENSOR_MAP_L2_PROMOTION_L2_128B, CU_TENSOR_MAP_FLOAT_OOB_FILL_NONE);
        cfg = 1;
    }

    int tiles64 = (n + 63) / 64;
    prepconv_kernel<<<576, dim3(32, 8)>>>(W2, out);                      // 1
    layer1_kernel<<<2048, 256>>>(feats, W1, nbr, bids, n);               // 2
    gemm_kernel<<<dim3(40, 16), 256, SMEM_DYN>>>();                      // 3 sparse
    self_tma_kernel<<<dim3(2, tiles64), 256, SMEM_TMA>>>(s_mapA, s_mapB,
                                                         n, bids, out);  // 4 self (ncu)
    finalize_kernel<<<8, 256>>>(out);                                    // 5
}